// round 1
// baseline (speedup 1.0000x reference)
#include <cuda_runtime.h>
#include <math.h>

#define NND 4096
#define F_IND 1433
#define HIDD 256
#define EMBD 16
#define KCD 10

// ---------------- scratch (static device allocations; no cudaMalloc) ----------
__device__ float g_h1[(size_t)NND * HIDD];          // x@W1
__device__ float g_h1o[(size_t)NND * HIDD];         // elu(att1@h1)
__device__ float g_h2[(size_t)NND * EMBD];          // h1o@W2
__device__ float g_h2o[(size_t)NND * EMBD];         // elu(att2@h2)
__device__ float g_s[NND];
__device__ float g_n[NND];
__device__ float g_att[(size_t)NND * NND];          // 64 MiB attention scratch

// ---------------- reductions ----------------
__device__ __forceinline__ float warp_red_sum(float v) {
    #pragma unroll
    for (int o = 16; o; o >>= 1) v += __shfl_xor_sync(0xffffffffu, v, o);
    return v;
}
__device__ __forceinline__ float warp_red_max(float v) {
    #pragma unroll
    for (int o = 16; o; o >>= 1) v = fmaxf(v, __shfl_xor_sync(0xffffffffu, v, o));
    return v;
}

// ---------------- SGEMM 128x128x8, 8x8 microtile, 256 threads ----------------
// ACT: 0 = none, 1 = ELU
template <int ACT>
__global__ __launch_bounds__(256) void sgemm128(
    const float* __restrict__ A, const float* __restrict__ B, float* __restrict__ C,
    int Mdim, int Ndim, int Kdim)
{
    __shared__ float As[8][128];
    __shared__ float Bs[8][128];

    const int bx = blockIdx.x;   // N tile
    const int by = blockIdx.y;   // M tile
    const int tid = threadIdx.x;
    const int tx = (tid & 15) << 3;   // 0..120
    const int ty = (tid >> 4) << 3;   // 0..120

    const int aRow = tid >> 1;          // 0..127
    const int aCol = (tid & 1) << 2;    // 0 or 4
    const int bRow = tid >> 5;          // 0..7
    const int bCol = (tid & 31) << 2;   // 0..124

    const float* Ab = A + (size_t)(by * 128) * Kdim;
    float acc[8][8];
    #pragma unroll
    for (int i = 0; i < 8; i++)
        #pragma unroll
        for (int j = 0; j < 8; j++) acc[i][j] = 0.f;

    for (int k0 = 0; k0 < Kdim; k0 += 8) {
        #pragma unroll
        for (int j = 0; j < 4; j++) {
            int gk = k0 + aCol + j;
            As[aCol + j][aRow] = (gk < Kdim) ? Ab[(size_t)aRow * Kdim + gk] : 0.f;
        }
        {
            int gk = k0 + bRow;
            bool okk = (gk < Kdim);
            const float* Brow = B + (size_t)gk * Ndim + bx * 128 + bCol;
            #pragma unroll
            for (int j = 0; j < 4; j++) {
                int gn = bx * 128 + bCol + j;
                Bs[bRow][bCol + j] = (okk && gn < Ndim) ? Brow[j] : 0.f;
            }
        }
        __syncthreads();
        #pragma unroll
        for (int kk = 0; kk < 8; kk++) {
            float ra[8], rb[8];
            #pragma unroll
            for (int i = 0; i < 8; i++) ra[i] = As[kk][ty + i];
            #pragma unroll
            for (int j = 0; j < 8; j++) rb[j] = Bs[kk][tx + j];
            #pragma unroll
            for (int i = 0; i < 8; i++)
                #pragma unroll
                for (int j = 0; j < 8; j++) acc[i][j] += ra[i] * rb[j];
        }
        __syncthreads();
    }

    #pragma unroll
    for (int i = 0; i < 8; i++) {
        int gm = by * 128 + ty + i;
        #pragma unroll
        for (int j = 0; j < 8; j++) {
            int gn = bx * 128 + tx + j;
            if (gn < Ndim) {
                float v = acc[i][j];
                if (ACT == 1) v = (v > 0.f) ? v : expm1f(v);
                C[(size_t)gm * Ndim + gn] = v;
            }
        }
    }
}

// ---------------- per-row attention scores: s = h@a_self, n = h@a_neigh -------
// D = 256: one block per row
__global__ __launch_bounds__(256) void rowvec256(
    const float* __restrict__ h, const float* __restrict__ a_self,
    const float* __restrict__ a_neigh, float* __restrict__ s, float* __restrict__ n)
{
    __shared__ float reds[8], redn[8];
    int row = blockIdx.x;
    int tid = threadIdx.x;
    float v = h[(size_t)row * 256 + tid];
    float ps = v * a_self[tid];
    float pn = v * a_neigh[tid];
    ps = warp_red_sum(ps);
    pn = warp_red_sum(pn);
    if ((tid & 31) == 0) { reds[tid >> 5] = ps; redn[tid >> 5] = pn; }
    __syncthreads();
    if (tid == 0) {
        float as = 0.f, an = 0.f;
        #pragma unroll
        for (int i = 0; i < 8; i++) { as += reds[i]; an += redn[i]; }
        s[row] = as; n[row] = an;
    }
}

// D = 16: 16 rows per block (256 threads, 16 lanes per row)
__global__ __launch_bounds__(256) void rowvec16(
    const float* __restrict__ h, const float* __restrict__ a_self,
    const float* __restrict__ a_neigh, float* __restrict__ s, float* __restrict__ n)
{
    int tid = threadIdx.x;
    int row = blockIdx.x * 16 + (tid >> 4);
    int d = tid & 15;
    float v = h[(size_t)row * 16 + d];
    float ps = v * a_self[d];
    float pn = v * a_neigh[d];
    #pragma unroll
    for (int o = 8; o; o >>= 1) {
        ps += __shfl_xor_sync(0xffffffffu, ps, o);
        pn += __shfl_xor_sync(0xffffffffu, pn, o);
    }
    if (d == 0) { s[row] = ps; n[row] = pn; }
}

// ---------------- masked leaky-relu logits + row softmax ----------------------
__global__ __launch_bounds__(256) void att_softmax(
    const float* __restrict__ s, const float* __restrict__ n,
    const float* __restrict__ Mm, const float* __restrict__ adj,
    float* __restrict__ att)
{
    __shared__ float buf[NND];
    __shared__ float red[8];
    int row = blockIdx.x;
    int tid = threadIdx.x;
    float si = s[row];
    const float* Mr = Mm + (size_t)row * NND;
    const float* Ar = adj + (size_t)row * NND;

    float lmax = -INFINITY;
    for (int j = tid; j < NND; j += 256) {
        float l = (si + n[j]) * Mr[j];
        l = (l >= 0.f) ? l : 0.2f * l;
        if (!(Ar[j] > 0.f)) l = -9e15f;
        buf[j] = l;
        lmax = fmaxf(lmax, l);
    }
    lmax = warp_red_max(lmax);
    if ((tid & 31) == 0) red[tid >> 5] = lmax;
    __syncthreads();
    if (tid < 32) {
        float v = (tid < 8) ? red[tid] : -INFINITY;
        v = warp_red_max(v);
        if (tid == 0) red[0] = v;
    }
    __syncthreads();
    lmax = red[0];
    __syncthreads();   // red reuse below

    float lsum = 0.f;
    for (int j = tid; j < NND; j += 256) {
        float e = __expf(buf[j] - lmax);
        buf[j] = e;
        lsum += e;
    }
    lsum = warp_red_sum(lsum);
    if ((tid & 31) == 0) red[tid >> 5] = lsum;
    __syncthreads();
    if (tid < 32) {
        float v = (tid < 8) ? red[tid] : 0.f;
        v = warp_red_sum(v);
        if (tid == 0) red[0] = v;
    }
    __syncthreads();
    float inv = 1.f / red[0];
    float* Or = att + (size_t)row * NND;
    for (int j = tid; j < NND; j += 256) Or[j] = buf[j] * inv;
}

// ---------------- GEMM with N = 16 (B tile cached in smem) --------------------
// A: [4096, K], B: [K, 16], C: [4096, 16].  K multiple of 128.  ACT 0/1 (ELU)
template <int ACT>
__global__ __launch_bounds__(256) void gemm_n16(
    const float* __restrict__ A, const float* __restrict__ B, float* __restrict__ C,
    int Kdim)
{
    __shared__ float Bs[128][16];
    int tid = threadIdx.x;
    int r = tid >> 4;            // 0..15
    int c = tid & 15;            // 0..15
    int row = blockIdx.x * 16 + r;
    const float* Arow = A + (size_t)row * Kdim;
    float acc = 0.f;

    for (int k0 = 0; k0 < Kdim; k0 += 128) {
        #pragma unroll
        for (int i = tid; i < 128 * 16; i += 256) {
            Bs[i >> 4][i & 15] = B[(size_t)(k0 + (i >> 4)) * 16 + (i & 15)];
        }
        __syncthreads();
        #pragma unroll 8
        for (int kk = 0; kk < 128; kk += 4) {
            float4 a = *reinterpret_cast<const float4*>(Arow + k0 + kk);
            acc += a.x * Bs[kk][c] + a.y * Bs[kk + 1][c]
                 + a.z * Bs[kk + 2][c] + a.w * Bs[kk + 3][c];
        }
        __syncthreads();
    }
    float v = acc;
    if (ACT == 1) v = (v > 0.f) ? v : expm1f(v);
    C[(size_t)row * 16 + c] = v;
}

// ---------------- L2 row-normalize (D=16) -------------------------------------
__global__ __launch_bounds__(256) void normalize_z(
    const float* __restrict__ h, float* __restrict__ z)
{
    int tid = threadIdx.x;
    int row = blockIdx.x * 16 + (tid >> 4);
    int d = tid & 15;
    float v = h[(size_t)row * 16 + d];
    float ss = v * v;
    #pragma unroll
    for (int o = 8; o; o >>= 1) ss += __shfl_xor_sync(0xffffffffu, ss, o);
    float nrm = fmaxf(sqrtf(ss), 1e-12f);
    z[(size_t)row * 16 + d] = v / nrm;
}

// ---------------- A_pred = sigmoid(z z^T) -------------------------------------
__global__ __launch_bounds__(256) void a_pred_kernel(
    const float* __restrict__ z, float* __restrict__ out)
{
    __shared__ float zi[64][17];
    __shared__ float zj[64][17];
    int bi = blockIdx.y * 64, bj = blockIdx.x * 64;
    for (int i = threadIdx.x; i < 64 * 16; i += 256) {
        int r = i >> 4, c = i & 15;
        zi[r][c] = z[(size_t)(bi + r) * 16 + c];
        zj[r][c] = z[(size_t)(bj + r) * 16 + c];
    }
    __syncthreads();
    int tr = (threadIdx.x >> 4) << 2;
    int tc = (threadIdx.x & 15) << 2;
    float acc[4][4];
    #pragma unroll
    for (int i = 0; i < 4; i++)
        #pragma unroll
        for (int j = 0; j < 4; j++) acc[i][j] = 0.f;
    #pragma unroll
    for (int k = 0; k < 16; k++) {
        float ri[4], rj[4];
        #pragma unroll
        for (int i = 0; i < 4; i++) ri[i] = zi[tr + i][k];
        #pragma unroll
        for (int j = 0; j < 4; j++) rj[j] = zj[tc + j][k];
        #pragma unroll
        for (int i = 0; i < 4; i++)
            #pragma unroll
            for (int j = 0; j < 4; j++) acc[i][j] += ri[i] * rj[j];
    }
    #pragma unroll
    for (int i = 0; i < 4; i++) {
        float4 v;
        v.x = 1.f / (1.f + __expf(-acc[i][0]));
        v.y = 1.f / (1.f + __expf(-acc[i][1]));
        v.z = 1.f / (1.f + __expf(-acc[i][2]));
        v.w = 1.f / (1.f + __expf(-acc[i][3]));
        *reinterpret_cast<float4*>(&out[(size_t)(bi + tr + i) * NND + bj + tc]) = v;
    }
}

// ---------------- Student-t soft assignment q ---------------------------------
__global__ __launch_bounds__(128) void q_kernel(
    const float* __restrict__ z, const float* __restrict__ clusters,
    float* __restrict__ q)
{
    int row = blockIdx.x * 128 + threadIdx.x;
    if (row >= NND) return;
    float zr[16];
    #pragma unroll
    for (int d = 0; d < 16; d++) zr[d] = z[(size_t)row * 16 + d];
    float qv[KCD];
    float ssum = 0.f;
    #pragma unroll
    for (int k = 0; k < KCD; k++) {
        float d2 = 0.f;
        #pragma unroll
        for (int d = 0; d < 16; d++) {
            float df = zr[d] - clusters[k * 16 + d];
            d2 += df * df;
        }
        // V = 1: q = (1/(1+d2))^((V+1)/2) = 1/(1+d2)
        float qk = 1.f / (1.f + d2);
        qv[k] = qk;
        ssum += qk;
    }
    float inv = 1.f / ssum;
    #pragma unroll
    for (int k = 0; k < KCD; k++) q[(size_t)row * KCD + k] = qv[k] * inv;
}

// ---------------- launch ------------------------------------------------------
extern "C" void kernel_launch(void* const* d_in, const int* in_sizes, int n_in,
                              void* d_out, int out_size)
{
    const float* x        = (const float*)d_in[0];
    const float* adj      = (const float*)d_in[1];
    const float* Mm       = (const float*)d_in[2];
    const float* W1       = (const float*)d_in[3];
    const float* a_self1  = (const float*)d_in[4];
    const float* a_neigh1 = (const float*)d_in[5];
    const float* W2       = (const float*)d_in[6];
    const float* a_self2  = (const float*)d_in[7];
    const float* a_neigh2 = (const float*)d_in[8];
    const float* clusters = (const float*)d_in[9];

    float* out    = (float*)d_out;
    float* A_pred = out;
    float* z      = out + (size_t)NND * NND;
    float* q      = z + (size_t)NND * EMBD;

    float *h1, *h1o, *h2, *h2o, *s, *n, *att;
    cudaGetSymbolAddress((void**)&h1,  g_h1);
    cudaGetSymbolAddress((void**)&h1o, g_h1o);
    cudaGetSymbolAddress((void**)&h2,  g_h2);
    cudaGetSymbolAddress((void**)&h2o, g_h2o);
    cudaGetSymbolAddress((void**)&s,   g_s);
    cudaGetSymbolAddress((void**)&n,   g_n);
    cudaGetSymbolAddress((void**)&att, g_att);

    // Layer 1
    sgemm128<0><<<dim3(2, 32), 256>>>(x, W1, h1, NND, HIDD, F_IND);
    rowvec256<<<NND, 256>>>(h1, a_self1, a_neigh1, s, n);
    att_softmax<<<NND, 256>>>(s, n, Mm, adj, att);
    sgemm128<1><<<dim3(2, 32), 256>>>(att, h1, h1o, NND, HIDD, NND);

    // Layer 2
    gemm_n16<0><<<NND / 16, 256>>>(h1o, W2, h2, HIDD);
    rowvec16<<<NND / 16, 256>>>(h2, a_self2, a_neigh2, s, n);
    att_softmax<<<NND, 256>>>(s, n, Mm, adj, att);
    gemm_n16<1><<<NND / 16, 256>>>(att, h2, h2o, NND);

    // Outputs
    normalize_z<<<NND / 16, 256>>>(h2o, z);
    a_pred_kernel<<<dim3(64, 64), 256>>>(z, A_pred);
    q_kernel<<<NND / 128, 128>>>(z, clusters, q);
}

// round 4
// speedup vs baseline: 2.2376x; 2.2376x over previous
#include <cuda_runtime.h>
#include <stdint.h>
#include <math.h>

#define NND 4096
#define F_IND 1433
#define KPAD 1440
#define HIDD 256
#define EMBD 16
#define KCD 10

// ---------------- scratch (static device allocations; no cudaMalloc) ----------
__device__ float g_h1[(size_t)NND * HIDD];          // x@W1
__device__ float g_h1o[(size_t)NND * HIDD];         // elu(att1@h1)
__device__ float g_h2[(size_t)NND * EMBD];          // h1o@W2
__device__ float g_h2o[(size_t)NND * EMBD];         // elu(att2@h2)
__device__ float g_s[NND];
__device__ float g_n[NND];
__device__ float g_att[(size_t)NND * NND];          // 64 MiB attention scratch / x_pad

// ---------------- reductions ----------------
__device__ __forceinline__ float warp_red_sum(float v) {
    #pragma unroll
    for (int o = 16; o; o >>= 1) v += __shfl_xor_sync(0xffffffffu, v, o);
    return v;
}
__device__ __forceinline__ float warp_red_max(float v) {
    #pragma unroll
    for (int o = 16; o; o >>= 1) v = fmaxf(v, __shfl_xor_sync(0xffffffffu, v, o));
    return v;
}

// ================= 3xTF32 tensor-core GEMM (mma.sync m16n8k8) =================
// C[M,256] = A[M,K] * B[K,256] ; fp32 in/out, ~fp32 accuracy via hi/lo split:
//   A = Ah + Al (Ah = tf32 round), acc += Ah*Bh + Ah*Bl + Al*Bh
// CTA tile 128x64, 8 warps (2x4), warp tile 64x16, BK=32, 3-stage cp.async.
#define BM 128
#define BN 64
#define BKT 32
#define STAGES 3
#define ALDP 36          // A smem row stride (floats): conflict-free
#define BLDP 72          // B smem row stride (floats): conflict-free
#define A_STAGE (BM * ALDP)
#define B_STAGE (BKT * BLDP)
#define GEMM_SMEM_BYTES (STAGES * (A_STAGE + B_STAGE) * 4)

__device__ __forceinline__ void cp_commit() {
    asm volatile("cp.async.commit_group;\n" ::: "memory");
}
template <int N>
__device__ __forceinline__ void cp_wait() {
    asm volatile("cp.async.wait_group %0;\n" :: "n"(N) : "memory");
}
__device__ __forceinline__ void cp16(uint32_t saddr, const void* gaddr) {
    asm volatile("cp.async.cg.shared.global [%0], [%1], 16;\n"
                 :: "r"(saddr), "l"(gaddr) : "memory");
}
__device__ __forceinline__ void cp16z(uint32_t saddr, const void* gaddr, int srcsz) {
    asm volatile("cp.async.cg.shared.global [%0], [%1], 16, %2;\n"
                 :: "r"(saddr), "l"(gaddr), "r"(srcsz) : "memory");
}
__device__ __forceinline__ float tf32_hi(float a) {
    float r;
    asm("cvt.rna.tf32.f32 %0, %1;\n" : "=f"(r) : "f"(a));
    return r;
}
__device__ __forceinline__ void mma8(float* d, const uint32_t* a, const uint32_t* b) {
    asm volatile(
        "mma.sync.aligned.m16n8k8.row.col.f32.tf32.tf32.f32 "
        "{%0,%1,%2,%3}, {%4,%5,%6,%7}, {%8,%9}, {%0,%1,%2,%3};\n"
        : "+f"(d[0]), "+f"(d[1]), "+f"(d[2]), "+f"(d[3])
        : "r"(a[0]), "r"(a[1]), "r"(a[2]), "r"(a[3]), "r"(b[0]), "r"(b[1]));
}

// ACT: 0 none, 1 ELU
template <int ACT>
__global__ __launch_bounds__(256) void mma_gemm(
    const float* __restrict__ A, const float* __restrict__ B, float* __restrict__ C,
    int Kreal, int Ktiles, int lda)
{
    extern __shared__ float smem[];
    float* As = smem;
    float* Bs = smem + STAGES * A_STAGE;
    const uint32_t sA0 = (uint32_t)__cvta_generic_to_shared(As);
    const uint32_t sB0 = (uint32_t)__cvta_generic_to_shared(Bs);

    const int tid = threadIdx.x;
    const int m0 = blockIdx.y * BM;
    const int n0 = blockIdx.x * BN;

    const int lane = tid & 31, wid = tid >> 5;
    const int wm = (wid >> 2) * 64;     // 0 / 64
    const int wn = (wid & 3) * 16;      // 0..48
    const int lr = lane >> 2;           // 0..7
    const int lc = lane & 3;            // 0..3

    float acc[4][2][4];
    #pragma unroll
    for (int i = 0; i < 4; i++)
        #pragma unroll
        for (int j = 0; j < 2; j++)
            #pragma unroll
            for (int e = 0; e < 4; e++) acc[i][j][e] = 0.f;

    auto load_tile = [&](int s, int k0) {
        uint32_t aBase = sA0 + s * A_STAGE * 4;
        #pragma unroll
        for (int j = 0; j < 4; j++) {
            int q = tid + 256 * j;           // 0..1023
            int r = q >> 3, c16 = q & 7;
            cp16(aBase + (r * ALDP + c16 * 4) * 4,
                 A + (size_t)(m0 + r) * lda + k0 + c16 * 4);
        }
        uint32_t bBase = sB0 + s * B_STAGE * 4;
        #pragma unroll
        for (int j = 0; j < 2; j++) {
            int q = tid + 256 * j;
            int r = q >> 4, c16 = q & 15;
            int gk = k0 + r;
            int sz = (gk < Kreal) ? 16 : 0;
            cp16z(bBase + (r * BLDP + c16 * 4) * 4,
                  B + (size_t)gk * 256 + n0 + c16 * 4, sz);
        }
    };

    load_tile(0, 0); cp_commit();
    load_tile(1, BKT); cp_commit();

    for (int it = 0; it < Ktiles; ++it) {
        if (it + 1 < Ktiles) cp_wait<1>(); else cp_wait<0>();
        __syncthreads();
        if (it + 2 < Ktiles) { load_tile((it + 2) % STAGES, (it + 2) * BKT); cp_commit(); }

        const float* As_ = As + (it % STAGES) * A_STAGE;
        const float* Bs_ = Bs + (it % STAGES) * B_STAGE;

        #pragma unroll
        for (int kk = 0; kk < BKT; kk += 8) {
            uint32_t afh[4][4], afl[4][4], bfh[2][2], bfl[2][2];
            #pragma unroll
            for (int i = 0; i < 4; i++) {
                const float* p = As_ + (wm + 16 * i + lr) * ALDP + kk + lc;
                float v0 = p[0], v1 = p[8 * ALDP], v2 = p[4], v3 = p[8 * ALDP + 4];
                float h0 = tf32_hi(v0), h1 = tf32_hi(v1), h2 = tf32_hi(v2), h3 = tf32_hi(v3);
                afh[i][0] = __float_as_uint(h0); afl[i][0] = __float_as_uint(v0 - h0);
                afh[i][1] = __float_as_uint(h1); afl[i][1] = __float_as_uint(v1 - h1);
                afh[i][2] = __float_as_uint(h2); afl[i][2] = __float_as_uint(v2 - h2);
                afh[i][3] = __float_as_uint(h3); afl[i][3] = __float_as_uint(v3 - h3);
            }
            #pragma unroll
            for (int j = 0; j < 2; j++) {
                const float* p = Bs_ + (kk + lc) * BLDP + wn + 8 * j + lr;
                float v0 = p[0], v1 = p[4 * BLDP];
                float h0 = tf32_hi(v0), h1 = tf32_hi(v1);
                bfh[j][0] = __float_as_uint(h0); bfl[j][0] = __float_as_uint(v0 - h0);
                bfh[j][1] = __float_as_uint(h1); bfl[j][1] = __float_as_uint(v1 - h1);
            }
            #pragma unroll
            for (int i = 0; i < 4; i++)
                #pragma unroll
                for (int j = 0; j < 2; j++) {
                    mma8(acc[i][j], afl[i], bfh[j]);
                    mma8(acc[i][j], afh[i], bfl[j]);
                    mma8(acc[i][j], afh[i], bfh[j]);
                }
        }
        __syncthreads();
    }

    // epilogue
    #pragma unroll
    for (int i = 0; i < 4; i++) {
        int r0 = m0 + wm + 16 * i + lr;
        #pragma unroll
        for (int j = 0; j < 2; j++) {
            int c0 = n0 + wn + 8 * j + 2 * lc;
            float v00 = acc[i][j][0], v01 = acc[i][j][1];
            float v10 = acc[i][j][2], v11 = acc[i][j][3];
            if (ACT == 1) {
                v00 = (v00 > 0.f) ? v00 : expm1f(v00);
                v01 = (v01 > 0.f) ? v01 : expm1f(v01);
                v10 = (v10 > 0.f) ? v10 : expm1f(v10);
                v11 = (v11 > 0.f) ? v11 : expm1f(v11);
            }
            *reinterpret_cast<float2*>(&C[(size_t)r0 * 256 + c0]) = make_float2(v00, v01);
            *reinterpret_cast<float2*>(&C[(size_t)(r0 + 8) * 256 + c0]) = make_float2(v10, v11);
        }
    }
}

// ---------------- pad x into [4096,1440] (zero tail) --------------------------
__global__ __launch_bounds__(256) void pad_x_kernel(
    const float* __restrict__ x, float* __restrict__ xp)
{
    int idx = blockIdx.x * 256 + threadIdx.x;
    if (idx >= NND * KPAD) return;
    int r = idx / KPAD, c = idx - r * KPAD;
    xp[idx] = (c < F_IND) ? x[(size_t)r * F_IND + c] : 0.f;
}

// ---------------- per-row attention scores ------------------------------------
__global__ __launch_bounds__(256) void rowvec256(
    const float* __restrict__ h, const float* __restrict__ a_self,
    const float* __restrict__ a_neigh, float* __restrict__ s, float* __restrict__ n)
{
    __shared__ float reds[8], redn[8];
    int row = blockIdx.x;
    int tid = threadIdx.x;
    float v = h[(size_t)row * 256 + tid];
    float ps = v * a_self[tid];
    float pn = v * a_neigh[tid];
    ps = warp_red_sum(ps);
    pn = warp_red_sum(pn);
    if ((tid & 31) == 0) { reds[tid >> 5] = ps; redn[tid >> 5] = pn; }
    __syncthreads();
    if (tid == 0) {
        float as = 0.f, an = 0.f;
        #pragma unroll
        for (int i = 0; i < 8; i++) { as += reds[i]; an += redn[i]; }
        s[row] = as; n[row] = an;
    }
}

__global__ __launch_bounds__(256) void rowvec16(
    const float* __restrict__ h, const float* __restrict__ a_self,
    const float* __restrict__ a_neigh, float* __restrict__ s, float* __restrict__ n)
{
    int tid = threadIdx.x;
    int row = blockIdx.x * 16 + (tid >> 4);
    int d = tid & 15;
    float v = h[(size_t)row * 16 + d];
    float ps = v * a_self[d];
    float pn = v * a_neigh[d];
    #pragma unroll
    for (int o = 8; o; o >>= 1) {
        ps += __shfl_xor_sync(0xffffffffu, ps, o);
        pn += __shfl_xor_sync(0xffffffffu, pn, o);
    }
    if (d == 0) { s[row] = ps; n[row] = pn; }
}

// ---------------- masked leaky-relu logits + row softmax ----------------------
__global__ __launch_bounds__(256) void att_softmax(
    const float* __restrict__ s, const float* __restrict__ n,
    const float* __restrict__ Mm, const float* __restrict__ adj,
    float* __restrict__ att)
{
    __shared__ float buf[NND];
    __shared__ float red[8];
    int row = blockIdx.x;
    int tid = threadIdx.x;
    float si = s[row];
    const float* Mr = Mm + (size_t)row * NND;
    const float* Ar = adj + (size_t)row * NND;

    float lmax = -INFINITY;
    for (int j = tid; j < NND; j += 256) {
        float l = (si + n[j]) * Mr[j];
        l = (l >= 0.f) ? l : 0.2f * l;
        if (!(Ar[j] > 0.f)) l = -9e15f;
        buf[j] = l;
        lmax = fmaxf(lmax, l);
    }
    lmax = warp_red_max(lmax);
    if ((tid & 31) == 0) red[tid >> 5] = lmax;
    __syncthreads();
    if (tid < 32) {
        float v = (tid < 8) ? red[tid] : -INFINITY;
        v = warp_red_max(v);
        if (tid == 0) red[0] = v;
    }
    __syncthreads();
    lmax = red[0];
    __syncthreads();

    float lsum = 0.f;
    for (int j = tid; j < NND; j += 256) {
        float e = __expf(buf[j] - lmax);
        buf[j] = e;
        lsum += e;
    }
    lsum = warp_red_sum(lsum);
    if ((tid & 31) == 0) red[tid >> 5] = lsum;
    __syncthreads();
    if (tid < 32) {
        float v = (tid < 8) ? red[tid] : 0.f;
        v = warp_red_sum(v);
        if (tid == 0) red[0] = v;
    }
    __syncthreads();
    float inv = 1.f / red[0];
    float* Or = att + (size_t)row * NND;
    for (int j = tid; j < NND; j += 256) Or[j] = buf[j] * inv;
}

// ---------------- GEMM with N = 16 --------------------------------------------
template <int ACT>
__global__ __launch_bounds__(256) void gemm_n16(
    const float* __restrict__ A, const float* __restrict__ B, float* __restrict__ C,
    int Kdim)
{
    __shared__ float Bs[128][16];
    int tid = threadIdx.x;
    int r = tid >> 4;
    int c = tid & 15;
    int row = blockIdx.x * 16 + r;
    const float* Arow = A + (size_t)row * Kdim;
    float acc = 0.f;

    for (int k0 = 0; k0 < Kdim; k0 += 128) {
        #pragma unroll
        for (int i = tid; i < 128 * 16; i += 256) {
            Bs[i >> 4][i & 15] = B[(size_t)(k0 + (i >> 4)) * 16 + (i & 15)];
        }
        __syncthreads();
        #pragma unroll 8
        for (int kk = 0; kk < 128; kk += 4) {
            float4 a = *reinterpret_cast<const float4*>(Arow + k0 + kk);
            acc += a.x * Bs[kk][c] + a.y * Bs[kk + 1][c]
                 + a.z * Bs[kk + 2][c] + a.w * Bs[kk + 3][c];
        }
        __syncthreads();
    }
    float v = acc;
    if (ACT == 1) v = (v > 0.f) ? v : expm1f(v);
    C[(size_t)row * 16 + c] = v;
}

// ---------------- L2 row-normalize (D=16) -------------------------------------
__global__ __launch_bounds__(256) void normalize_z(
    const float* __restrict__ h, float* __restrict__ z)
{
    int tid = threadIdx.x;
    int row = blockIdx.x * 16 + (tid >> 4);
    int d = tid & 15;
    float v = h[(size_t)row * 16 + d];
    float ss = v * v;
    #pragma unroll
    for (int o = 8; o; o >>= 1) ss += __shfl_xor_sync(0xffffffffu, ss, o);
    float nrm = fmaxf(sqrtf(ss), 1e-12f);
    z[(size_t)row * 16 + d] = v / nrm;
}

// ---------------- A_pred = sigmoid(z z^T) -------------------------------------
__global__ __launch_bounds__(256) void a_pred_kernel(
    const float* __restrict__ z, float* __restrict__ out)
{
    __shared__ float zi[64][17];
    __shared__ float zj[64][17];
    int bi = blockIdx.y * 64, bj = blockIdx.x * 64;
    for (int i = threadIdx.x; i < 64 * 16; i += 256) {
        int r = i >> 4, c = i & 15;
        zi[r][c] = z[(size_t)(bi + r) * 16 + c];
        zj[r][c] = z[(size_t)(bj + r) * 16 + c];
    }
    __syncthreads();
    int tr = (threadIdx.x >> 4) << 2;
    int tc = (threadIdx.x & 15) << 2;
    float acc[4][4];
    #pragma unroll
    for (int i = 0; i < 4; i++)
        #pragma unroll
        for (int j = 0; j < 4; j++) acc[i][j] = 0.f;
    #pragma unroll
    for (int k = 0; k < 16; k++) {
        float ri[4], rj[4];
        #pragma unroll
        for (int i = 0; i < 4; i++) ri[i] = zi[tr + i][k];
        #pragma unroll
        for (int j = 0; j < 4; j++) rj[j] = zj[tc + j][k];
        #pragma unroll
        for (int i = 0; i < 4; i++)
            #pragma unroll
            for (int j = 0; j < 4; j++) acc[i][j] += ri[i] * rj[j];
    }
    #pragma unroll
    for (int i = 0; i < 4; i++) {
        float4 v;
        v.x = 1.f / (1.f + __expf(-acc[i][0]));
        v.y = 1.f / (1.f + __expf(-acc[i][1]));
        v.z = 1.f / (1.f + __expf(-acc[i][2]));
        v.w = 1.f / (1.f + __expf(-acc[i][3]));
        *reinterpret_cast<float4*>(&out[(size_t)(bi + tr + i) * NND + bj + tc]) = v;
    }
}

// ---------------- Student-t soft assignment q ---------------------------------
__global__ __launch_bounds__(128) void q_kernel(
    const float* __restrict__ z, const float* __restrict__ clusters,
    float* __restrict__ q)
{
    int row = blockIdx.x * 128 + threadIdx.x;
    if (row >= NND) return;
    float zr[16];
    #pragma unroll
    for (int d = 0; d < 16; d++) zr[d] = z[(size_t)row * 16 + d];
    float qv[KCD];
    float ssum = 0.f;
    #pragma unroll
    for (int k = 0; k < KCD; k++) {
        float d2 = 0.f;
        #pragma unroll
        for (int d = 0; d < 16; d++) {
            float df = zr[d] - clusters[k * 16 + d];
            d2 += df * df;
        }
        float qk = 1.f / (1.f + d2);
        qv[k] = qk;
        ssum += qk;
    }
    float inv = 1.f / ssum;
    #pragma unroll
    for (int k = 0; k < KCD; k++) q[(size_t)row * KCD + k] = qv[k] * inv;
}

// ---------------- launch ------------------------------------------------------
extern "C" void kernel_launch(void* const* d_in, const int* in_sizes, int n_in,
                              void* d_out, int out_size)
{
    const float* x        = (const float*)d_in[0];
    const float* adj      = (const float*)d_in[1];
    const float* Mm       = (const float*)d_in[2];
    const float* W1       = (const float*)d_in[3];
    const float* a_self1  = (const float*)d_in[4];
    const float* a_neigh1 = (const float*)d_in[5];
    const float* W2       = (const float*)d_in[6];
    const float* a_self2  = (const float*)d_in[7];
    const float* a_neigh2 = (const float*)d_in[8];
    const float* clusters = (const float*)d_in[9];

    float* out    = (float*)d_out;
    float* A_pred = out;
    float* z      = out + (size_t)NND * NND;
    float* q      = z + (size_t)NND * EMBD;

    float *h1, *h1o, *h2, *h2o, *s, *n, *att;
    cudaGetSymbolAddress((void**)&h1,  g_h1);
    cudaGetSymbolAddress((void**)&h1o, g_h1o);
    cudaGetSymbolAddress((void**)&h2,  g_h2);
    cudaGetSymbolAddress((void**)&h2o, g_h2o);
    cudaGetSymbolAddress((void**)&s,   g_s);
    cudaGetSymbolAddress((void**)&n,   g_n);
    cudaGetSymbolAddress((void**)&att, g_att);

    cudaFuncSetAttribute(mma_gemm<0>, cudaFuncAttributeMaxDynamicSharedMemorySize, GEMM_SMEM_BYTES);
    cudaFuncSetAttribute(mma_gemm<1>, cudaFuncAttributeMaxDynamicSharedMemorySize, GEMM_SMEM_BYTES);

    // Layer 1: h1 = x @ W1 (3xtf32 tensor cores, x zero-padded to K=1440)
    float* xpad = att;   // reuse 64MB scratch before att is written
    pad_x_kernel<<<(NND * KPAD + 255) / 256, 256>>>(x, xpad);
    mma_gemm<0><<<dim3(4, 32), 256, GEMM_SMEM_BYTES>>>(xpad, W1, h1, F_IND, KPAD / BKT, KPAD);
    rowvec256<<<NND, 256>>>(h1, a_self1, a_neigh1, s, n);
    att_softmax<<<NND, 256>>>(s, n, Mm, adj, att);
    mma_gemm<1><<<dim3(4, 32), 256, GEMM_SMEM_BYTES>>>(att, h1, h1o, NND, NND / BKT, NND);

    // Layer 2
    gemm_n16<0><<<NND / 16, 256>>>(h1o, W2, h2, HIDD);
    rowvec16<<<NND / 16, 256>>>(h2, a_self2, a_neigh2, s, n);
    att_softmax<<<NND, 256>>>(s, n, Mm, adj, att);
    gemm_n16<1><<<NND / 16, 256>>>(att, h2, h2o, NND);

    // Outputs
    normalize_z<<<NND / 16, 256>>>(h2o, z);
    a_pred_kernel<<<dim3(64, 64), 256>>>(z, A_pred);
    q_kernel<<<NND / 128, 128>>>(z, clusters, q);
}

// round 5
// speedup vs baseline: 7.5284x; 3.3645x over previous
#include <cuda_runtime.h>
#include <stdint.h>
#include <math.h>

#define NND 4096
#define F_IND 1433
#define KPAD 1440
#define HIDD 256
#define EMBD 16
#define KCD 10
#define NNZCAP 512

// ---------------- scratch (static device allocations; no cudaMalloc) ----------
__device__ float g_h1[(size_t)NND * HIDD];          // x@W1
__device__ float g_h1o[(size_t)NND * HIDD];         // elu(att1@h1)
__device__ float g_h2[(size_t)NND * EMBD];          // h1o@W2
__device__ float g_h2o[(size_t)NND * EMBD];         // elu(att2@h2)
__device__ float g_s[NND];
__device__ float g_n[NND];
__device__ float g_xpad[(size_t)NND * KPAD];        // padded x
__device__ int   g_nidx[(size_t)NND * NNZCAP];      // CSR col indices
__device__ int   g_ncnt[NND];                        // CSR row counts

// ---------------- reductions ----------------
__device__ __forceinline__ float warp_red_sum(float v) {
    #pragma unroll
    for (int o = 16; o; o >>= 1) v += __shfl_xor_sync(0xffffffffu, v, o);
    return v;
}
__device__ __forceinline__ float warp_red_max(float v) {
    #pragma unroll
    for (int o = 16; o; o >>= 1) v = fmaxf(v, __shfl_xor_sync(0xffffffffu, v, o));
    return v;
}

// ================= 3xTF32 tensor-core GEMM (mma.sync m16n8k8) =================
#define BM 128
#define BN 64
#define BKT 32
#define STAGES 3
#define ALDP 36
#define BLDP 72
#define A_STAGE (BM * ALDP)
#define B_STAGE (BKT * BLDP)
#define GEMM_SMEM_BYTES (STAGES * (A_STAGE + B_STAGE) * 4)

__device__ __forceinline__ void cp_commit() {
    asm volatile("cp.async.commit_group;\n" ::: "memory");
}
template <int N>
__device__ __forceinline__ void cp_wait() {
    asm volatile("cp.async.wait_group %0;\n" :: "n"(N) : "memory");
}
__device__ __forceinline__ void cp16(uint32_t saddr, const void* gaddr) {
    asm volatile("cp.async.cg.shared.global [%0], [%1], 16;\n"
                 :: "r"(saddr), "l"(gaddr) : "memory");
}
__device__ __forceinline__ void cp16z(uint32_t saddr, const void* gaddr, int srcsz) {
    asm volatile("cp.async.cg.shared.global [%0], [%1], 16, %2;\n"
                 :: "r"(saddr), "l"(gaddr), "r"(srcsz) : "memory");
}
__device__ __forceinline__ float tf32_hi(float a) {
    float r;
    asm("cvt.rna.tf32.f32 %0, %1;\n" : "=f"(r) : "f"(a));
    return r;
}
__device__ __forceinline__ void mma8(float* d, const uint32_t* a, const uint32_t* b) {
    asm volatile(
        "mma.sync.aligned.m16n8k8.row.col.f32.tf32.tf32.f32 "
        "{%0,%1,%2,%3}, {%4,%5,%6,%7}, {%8,%9}, {%0,%1,%2,%3};\n"
        : "+f"(d[0]), "+f"(d[1]), "+f"(d[2]), "+f"(d[3])
        : "r"(a[0]), "r"(a[1]), "r"(a[2]), "r"(a[3]), "r"(b[0]), "r"(b[1]));
}

__global__ __launch_bounds__(256) void mma_gemm(
    const float* __restrict__ A, const float* __restrict__ B, float* __restrict__ C,
    int Kreal, int Ktiles, int lda)
{
    extern __shared__ float smem[];
    float* As = smem;
    float* Bs = smem + STAGES * A_STAGE;
    const uint32_t sA0 = (uint32_t)__cvta_generic_to_shared(As);
    const uint32_t sB0 = (uint32_t)__cvta_generic_to_shared(Bs);

    const int tid = threadIdx.x;
    const int m0 = blockIdx.y * BM;
    const int n0 = blockIdx.x * BN;

    const int lane = tid & 31, wid = tid >> 5;
    const int wm = (wid >> 2) * 64;
    const int wn = (wid & 3) * 16;
    const int lr = lane >> 2;
    const int lc = lane & 3;

    float acc[4][2][4];
    #pragma unroll
    for (int i = 0; i < 4; i++)
        #pragma unroll
        for (int j = 0; j < 2; j++)
            #pragma unroll
            for (int e = 0; e < 4; e++) acc[i][j][e] = 0.f;

    auto load_tile = [&](int s, int k0) {
        uint32_t aBase = sA0 + s * A_STAGE * 4;
        #pragma unroll
        for (int j = 0; j < 4; j++) {
            int q = tid + 256 * j;
            int r = q >> 3, c16 = q & 7;
            cp16(aBase + (r * ALDP + c16 * 4) * 4,
                 A + (size_t)(m0 + r) * lda + k0 + c16 * 4);
        }
        uint32_t bBase = sB0 + s * B_STAGE * 4;
        #pragma unroll
        for (int j = 0; j < 2; j++) {
            int q = tid + 256 * j;
            int r = q >> 4, c16 = q & 15;
            int gk = k0 + r;
            int sz = (gk < Kreal) ? 16 : 0;
            cp16z(bBase + (r * BLDP + c16 * 4) * 4,
                  B + (size_t)gk * 256 + n0 + c16 * 4, sz);
        }
    };

    load_tile(0, 0); cp_commit();
    load_tile(1, BKT); cp_commit();

    for (int it = 0; it < Ktiles; ++it) {
        if (it + 1 < Ktiles) cp_wait<1>(); else cp_wait<0>();
        __syncthreads();
        if (it + 2 < Ktiles) { load_tile((it + 2) % STAGES, (it + 2) * BKT); cp_commit(); }

        const float* As_ = As + (it % STAGES) * A_STAGE;
        const float* Bs_ = Bs + (it % STAGES) * B_STAGE;

        #pragma unroll
        for (int kk = 0; kk < BKT; kk += 8) {
            uint32_t afh[4][4], afl[4][4], bfh[2][2], bfl[2][2];
            #pragma unroll
            for (int i = 0; i < 4; i++) {
                const float* p = As_ + (wm + 16 * i + lr) * ALDP + kk + lc;
                float v0 = p[0], v1 = p[8 * ALDP], v2 = p[4], v3 = p[8 * ALDP + 4];
                float h0 = tf32_hi(v0), h1 = tf32_hi(v1), h2 = tf32_hi(v2), h3 = tf32_hi(v3);
                afh[i][0] = __float_as_uint(h0); afl[i][0] = __float_as_uint(v0 - h0);
                afh[i][1] = __float_as_uint(h1); afl[i][1] = __float_as_uint(v1 - h1);
                afh[i][2] = __float_as_uint(h2); afl[i][2] = __float_as_uint(v2 - h2);
                afh[i][3] = __float_as_uint(h3); afl[i][3] = __float_as_uint(v3 - h3);
            }
            #pragma unroll
            for (int j = 0; j < 2; j++) {
                const float* p = Bs_ + (kk + lc) * BLDP + wn + 8 * j + lr;
                float v0 = p[0], v1 = p[4 * BLDP];
                float h0 = tf32_hi(v0), h1 = tf32_hi(v1);
                bfh[j][0] = __float_as_uint(h0); bfl[j][0] = __float_as_uint(v0 - h0);
                bfh[j][1] = __float_as_uint(h1); bfl[j][1] = __float_as_uint(v1 - h1);
            }
            #pragma unroll
            for (int i = 0; i < 4; i++)
                #pragma unroll
                for (int j = 0; j < 2; j++) {
                    mma8(acc[i][j], afl[i], bfh[j]);
                    mma8(acc[i][j], afh[i], bfl[j]);
                    mma8(acc[i][j], afh[i], bfh[j]);
                }
        }
        __syncthreads();
    }

    #pragma unroll
    for (int i = 0; i < 4; i++) {
        int r0 = m0 + wm + 16 * i + lr;
        #pragma unroll
        for (int j = 0; j < 2; j++) {
            int c0 = n0 + wn + 8 * j + 2 * lc;
            *reinterpret_cast<float2*>(&C[(size_t)r0 * 256 + c0]) =
                make_float2(acc[i][j][0], acc[i][j][1]);
            *reinterpret_cast<float2*>(&C[(size_t)(r0 + 8) * 256 + c0]) =
                make_float2(acc[i][j][2], acc[i][j][3]);
        }
    }
}

// ---------------- pad x into [4096,1440] --------------------------------------
__global__ __launch_bounds__(256) void pad_x_kernel(
    const float* __restrict__ x, float* __restrict__ xp)
{
    int idx = blockIdx.x * 256 + threadIdx.x;
    if (idx >= NND * KPAD) return;
    int r = idx / KPAD, c = idx - r * KPAD;
    xp[idx] = (c < F_IND) ? x[(size_t)r * F_IND + c] : 0.f;
}

// ---------------- CSR adjacency build (shared by both layers) -----------------
__global__ __launch_bounds__(256) void build_csr(
    const float* __restrict__ adj, int* __restrict__ nidx, int* __restrict__ ncnt)
{
    __shared__ int cnt;
    int row = blockIdx.x;
    if (threadIdx.x == 0) cnt = 0;
    __syncthreads();
    const float4* Ar = reinterpret_cast<const float4*>(adj + (size_t)row * NND);
    for (int j4 = threadIdx.x; j4 < NND / 4; j4 += 256) {
        float4 v = Ar[j4];
        if (v.x > 0.f) { int p = atomicAdd(&cnt, 1); if (p < NNZCAP) nidx[(size_t)row * NNZCAP + p] = j4 * 4; }
        if (v.y > 0.f) { int p = atomicAdd(&cnt, 1); if (p < NNZCAP) nidx[(size_t)row * NNZCAP + p] = j4 * 4 + 1; }
        if (v.z > 0.f) { int p = atomicAdd(&cnt, 1); if (p < NNZCAP) nidx[(size_t)row * NNZCAP + p] = j4 * 4 + 2; }
        if (v.w > 0.f) { int p = atomicAdd(&cnt, 1); if (p < NNZCAP) nidx[(size_t)row * NNZCAP + p] = j4 * 4 + 3; }
    }
    __syncthreads();
    if (threadIdx.x == 0) ncnt[row] = min(cnt, NNZCAP);
}

// ---------------- per-row attention scores ------------------------------------
__global__ __launch_bounds__(256) void rowvec256(
    const float* __restrict__ h, const float* __restrict__ a_self,
    const float* __restrict__ a_neigh, float* __restrict__ s, float* __restrict__ n)
{
    __shared__ float reds[8], redn[8];
    int row = blockIdx.x;
    int tid = threadIdx.x;
    float v = h[(size_t)row * 256 + tid];
    float ps = v * a_self[tid];
    float pn = v * a_neigh[tid];
    ps = warp_red_sum(ps);
    pn = warp_red_sum(pn);
    if ((tid & 31) == 0) { reds[tid >> 5] = ps; redn[tid >> 5] = pn; }
    __syncthreads();
    if (tid == 0) {
        float as = 0.f, an = 0.f;
        #pragma unroll
        for (int i = 0; i < 8; i++) { as += reds[i]; an += redn[i]; }
        s[row] = as; n[row] = an;
    }
}

__global__ __launch_bounds__(256) void rowvec16(
    const float* __restrict__ h, const float* __restrict__ a_self,
    const float* __restrict__ a_neigh, float* __restrict__ s, float* __restrict__ n)
{
    int tid = threadIdx.x;
    int row = blockIdx.x * 16 + (tid >> 4);
    int d = tid & 15;
    float v = h[(size_t)row * 16 + d];
    float ps = v * a_self[d];
    float pn = v * a_neigh[d];
    #pragma unroll
    for (int o = 8; o; o >>= 1) {
        ps += __shfl_xor_sync(0xffffffffu, ps, o);
        pn += __shfl_xor_sync(0xffffffffu, pn, o);
    }
    if (d == 0) { s[row] = ps; n[row] = pn; }
}

// ---- fused sparse softmax + SpMM, D=256: out[row,:] = ELU(softmax_row @ h) ---
__global__ __launch_bounds__(256) void sparse_att_h256(
    const float* __restrict__ s, const float* __restrict__ n,
    const float* __restrict__ Mm, const float* __restrict__ h,
    const int* __restrict__ nidx, const int* __restrict__ ncnt,
    float* __restrict__ out)
{
    __shared__ int sidx[NNZCAP];
    __shared__ float slog[NNZCAP];
    __shared__ float red[8];
    int row = blockIdx.x, tid = threadIdx.x;
    int cnt = ncnt[row];
    float si = s[row];
    const float* Mr = Mm + (size_t)row * NND;
    const int* Ir = nidx + (size_t)row * NNZCAP;

    float lmax = -INFINITY;
    for (int t = tid; t < cnt; t += 256) {
        int j = Ir[t];
        sidx[t] = j;
        float l = (si + n[j]) * Mr[j];
        l = (l >= 0.f) ? l : 0.2f * l;
        slog[t] = l;
        lmax = fmaxf(lmax, l);
    }
    lmax = warp_red_max(lmax);
    if ((tid & 31) == 0) red[tid >> 5] = lmax;
    __syncthreads();
    if (tid < 32) {
        float v = (tid < 8) ? red[tid] : -INFINITY;
        v = warp_red_max(v);
        if (tid == 0) red[0] = v;
    }
    __syncthreads();
    lmax = red[0];
    __syncthreads();
    float lsum = 0.f;
    for (int t = tid; t < cnt; t += 256) {
        float e = __expf(slog[t] - lmax);
        slog[t] = e;
        lsum += e;
    }
    lsum = warp_red_sum(lsum);
    if ((tid & 31) == 0) red[tid >> 5] = lsum;
    __syncthreads();
    if (tid < 32) {
        float v = (tid < 8) ? red[tid] : 0.f;
        v = warp_red_sum(v);
        if (tid == 0) red[0] = v;
    }
    __syncthreads();
    float inv = 1.f / red[0];

    // accumulate over neighbors; thread owns output dim = tid
    float acc = 0.f;
    int t = 0;
    for (; t + 4 <= cnt; t += 4) {
        float a0 = slog[t],     a1 = slog[t + 1];
        float a2 = slog[t + 2], a3 = slog[t + 3];
        const float* p0 = h + (size_t)sidx[t] * 256 + tid;
        const float* p1 = h + (size_t)sidx[t + 1] * 256 + tid;
        const float* p2 = h + (size_t)sidx[t + 2] * 256 + tid;
        const float* p3 = h + (size_t)sidx[t + 3] * 256 + tid;
        acc += a0 * p0[0] + a1 * p1[0] + a2 * p2[0] + a3 * p3[0];
    }
    for (; t < cnt; t++) acc += slog[t] * h[(size_t)sidx[t] * 256 + tid];
    acc *= inv;
    float v = (acc > 0.f) ? acc : expm1f(acc);
    out[(size_t)row * 256 + tid] = v;
}

// ---- fused sparse softmax + SpMM, D=16 ---------------------------------------
__global__ __launch_bounds__(128) void sparse_att_h16(
    const float* __restrict__ s, const float* __restrict__ n,
    const float* __restrict__ Mm, const float* __restrict__ h,
    const int* __restrict__ nidx, const int* __restrict__ ncnt,
    float* __restrict__ out)
{
    __shared__ int sidx[NNZCAP];
    __shared__ float slog[NNZCAP];
    __shared__ float red[4];
    __shared__ float part[8][16];
    int row = blockIdx.x, tid = threadIdx.x;
    int cnt = ncnt[row];
    float si = s[row];
    const float* Mr = Mm + (size_t)row * NND;
    const int* Ir = nidx + (size_t)row * NNZCAP;

    float lmax = -INFINITY;
    for (int t = tid; t < cnt; t += 128) {
        int j = Ir[t];
        sidx[t] = j;
        float l = (si + n[j]) * Mr[j];
        l = (l >= 0.f) ? l : 0.2f * l;
        slog[t] = l;
        lmax = fmaxf(lmax, l);
    }
    lmax = warp_red_max(lmax);
    if ((tid & 31) == 0) red[tid >> 5] = lmax;
    __syncthreads();
    if (tid < 32) {
        float v = (tid < 4) ? red[tid] : -INFINITY;
        v = warp_red_max(v);
        if (tid == 0) red[0] = v;
    }
    __syncthreads();
    lmax = red[0];
    __syncthreads();
    float lsum = 0.f;
    for (int t = tid; t < cnt; t += 128) {
        float e = __expf(slog[t] - lmax);
        slog[t] = e;
        lsum += e;
    }
    lsum = warp_red_sum(lsum);
    if ((tid & 31) == 0) red[tid >> 5] = lsum;
    __syncthreads();
    if (tid < 32) {
        float v = (tid < 4) ? red[tid] : 0.f;
        v = warp_red_sum(v);
        if (tid == 0) red[0] = v;
    }
    __syncthreads();
    float inv = 1.f / red[0];

    int p = tid >> 4, d = tid & 15;
    float acc = 0.f;
    for (int t = p; t < cnt; t += 8)
        acc += slog[t] * h[(size_t)sidx[t] * 16 + d];
    part[p][d] = acc;
    __syncthreads();
    if (tid < 16) {
        float a = 0.f;
        #pragma unroll
        for (int pp = 0; pp < 8; pp++) a += part[pp][tid];
        a *= inv;
        float v = (a > 0.f) ? a : expm1f(a);
        out[(size_t)row * 16 + tid] = v;
    }
}

// ---------------- GEMM with N = 16 (h1o @ W2, K=256) --------------------------
__global__ __launch_bounds__(256) void gemm_n16(
    const float* __restrict__ A, const float* __restrict__ B, float* __restrict__ C,
    int Kdim)
{
    __shared__ float Bs[128][16];
    int tid = threadIdx.x;
    int r = tid >> 4;
    int c = tid & 15;
    int row = blockIdx.x * 16 + r;
    const float* Arow = A + (size_t)row * Kdim;
    float acc = 0.f;

    for (int k0 = 0; k0 < Kdim; k0 += 128) {
        #pragma unroll
        for (int i = tid; i < 128 * 16; i += 256) {
            Bs[i >> 4][i & 15] = B[(size_t)(k0 + (i >> 4)) * 16 + (i & 15)];
        }
        __syncthreads();
        #pragma unroll 8
        for (int kk = 0; kk < 128; kk += 4) {
            float4 a = *reinterpret_cast<const float4*>(Arow + k0 + kk);
            acc += a.x * Bs[kk][c] + a.y * Bs[kk + 1][c]
                 + a.z * Bs[kk + 2][c] + a.w * Bs[kk + 3][c];
        }
        __syncthreads();
    }
    C[(size_t)row * 16 + c] = acc;
}

// ---------------- L2 row-normalize (D=16) -------------------------------------
__global__ __launch_bounds__(256) void normalize_z(
    const float* __restrict__ h, float* __restrict__ z)
{
    int tid = threadIdx.x;
    int row = blockIdx.x * 16 + (tid >> 4);
    int d = tid & 15;
    float v = h[(size_t)row * 16 + d];
    float ss = v * v;
    #pragma unroll
    for (int o = 8; o; o >>= 1) ss += __shfl_xor_sync(0xffffffffu, ss, o);
    float nrm = fmaxf(sqrtf(ss), 1e-12f);
    z[(size_t)row * 16 + d] = v / nrm;
}

// ---------------- A_pred = sigmoid(z z^T) -------------------------------------
__global__ __launch_bounds__(256) void a_pred_kernel(
    const float* __restrict__ z, float* __restrict__ out)
{
    __shared__ float zi[64][17];
    __shared__ float zj[64][17];
    int bi = blockIdx.y * 64, bj = blockIdx.x * 64;
    for (int i = threadIdx.x; i < 64 * 16; i += 256) {
        int r = i >> 4, c = i & 15;
        zi[r][c] = z[(size_t)(bi + r) * 16 + c];
        zj[r][c] = z[(size_t)(bj + r) * 16 + c];
    }
    __syncthreads();
    int tr = (threadIdx.x >> 4) << 2;
    int tc = (threadIdx.x & 15) << 2;
    float acc[4][4];
    #pragma unroll
    for (int i = 0; i < 4; i++)
        #pragma unroll
        for (int j = 0; j < 4; j++) acc[i][j] = 0.f;
    #pragma unroll
    for (int k = 0; k < 16; k++) {
        float ri[4], rj[4];
        #pragma unroll
        for (int i = 0; i < 4; i++) ri[i] = zi[tr + i][k];
        #pragma unroll
        for (int j = 0; j < 4; j++) rj[j] = zj[tc + j][k];
        #pragma unroll
        for (int i = 0; i < 4; i++)
            #pragma unroll
            for (int j = 0; j < 4; j++) acc[i][j] += ri[i] * rj[j];
    }
    #pragma unroll
    for (int i = 0; i < 4; i++) {
        float4 v;
        v.x = 1.f / (1.f + __expf(-acc[i][0]));
        v.y = 1.f / (1.f + __expf(-acc[i][1]));
        v.z = 1.f / (1.f + __expf(-acc[i][2]));
        v.w = 1.f / (1.f + __expf(-acc[i][3]));
        *reinterpret_cast<float4*>(&out[(size_t)(bi + tr + i) * NND + bj + tc]) = v;
    }
}

// ---------------- Student-t soft assignment q ---------------------------------
__global__ __launch_bounds__(128) void q_kernel(
    const float* __restrict__ z, const float* __restrict__ clusters,
    float* __restrict__ q)
{
    int row = blockIdx.x * 128 + threadIdx.x;
    if (row >= NND) return;
    float zr[16];
    #pragma unroll
    for (int d = 0; d < 16; d++) zr[d] = z[(size_t)row * 16 + d];
    float qv[KCD];
    float ssum = 0.f;
    #pragma unroll
    for (int k = 0; k < KCD; k++) {
        float d2 = 0.f;
        #pragma unroll
        for (int d = 0; d < 16; d++) {
            float df = zr[d] - clusters[k * 16 + d];
            d2 += df * df;
        }
        float qk = 1.f / (1.f + d2);
        qv[k] = qk;
        ssum += qk;
    }
    float inv = 1.f / ssum;
    #pragma unroll
    for (int k = 0; k < KCD; k++) q[(size_t)row * KCD + k] = qv[k] * inv;
}

// ---------------- launch ------------------------------------------------------
extern "C" void kernel_launch(void* const* d_in, const int* in_sizes, int n_in,
                              void* d_out, int out_size)
{
    const float* x        = (const float*)d_in[0];
    const float* adj      = (const float*)d_in[1];
    const float* Mm       = (const float*)d_in[2];
    const float* W1       = (const float*)d_in[3];
    const float* a_self1  = (const float*)d_in[4];
    const float* a_neigh1 = (const float*)d_in[5];
    const float* W2       = (const float*)d_in[6];
    const float* a_self2  = (const float*)d_in[7];
    const float* a_neigh2 = (const float*)d_in[8];
    const float* clusters = (const float*)d_in[9];

    float* out    = (float*)d_out;
    float* A_pred = out;
    float* z      = out + (size_t)NND * NND;
    float* q      = z + (size_t)NND * EMBD;

    float *h1, *h1o, *h2, *h2o, *s, *n, *xpad;
    int *nidx, *ncnt;
    cudaGetSymbolAddress((void**)&h1,   g_h1);
    cudaGetSymbolAddress((void**)&h1o,  g_h1o);
    cudaGetSymbolAddress((void**)&h2,   g_h2);
    cudaGetSymbolAddress((void**)&h2o,  g_h2o);
    cudaGetSymbolAddress((void**)&s,    g_s);
    cudaGetSymbolAddress((void**)&n,    g_n);
    cudaGetSymbolAddress((void**)&xpad, g_xpad);
    cudaGetSymbolAddress((void**)&nidx, g_nidx);
    cudaGetSymbolAddress((void**)&ncnt, g_ncnt);

    cudaFuncSetAttribute(mma_gemm, cudaFuncAttributeMaxDynamicSharedMemorySize, GEMM_SMEM_BYTES);

    // CSR structure (shared by both layers)
    build_csr<<<NND, 256>>>(adj, nidx, ncnt);

    // Layer 1: h1 = x @ W1 (3xtf32), then fused sparse softmax+SpMM
    pad_x_kernel<<<(NND * KPAD + 255) / 256, 256>>>(x, xpad);
    mma_gemm<<<dim3(4, 32), 256, GEMM_SMEM_BYTES>>>(xpad, W1, h1, F_IND, KPAD / BKT, KPAD);
    rowvec256<<<NND, 256>>>(h1, a_self1, a_neigh1, s, n);
    sparse_att_h256<<<NND, 256>>>(s, n, Mm, h1, nidx, ncnt, h1o);

    // Layer 2
    gemm_n16<<<NND / 16, 256>>>(h1o, W2, h2, HIDD);
    rowvec16<<<NND / 16, 256>>>(h2, a_self2, a_neigh2, s, n);
    sparse_att_h16<<<NND, 128>>>(s, n, Mm, h2, nidx, ncnt, h2o);

    // Outputs
    normalize_z<<<NND / 16, 256>>>(h2o, z);
    a_pred_kernel<<<dim3(64, 64), 256>>>(z, A_pred);
    q_kernel<<<NND / 128, 128>>>(z, clusters, q);
}

// round 6
// speedup vs baseline: 8.9834x; 1.1933x over previous
#include <cuda_runtime.h>
#include <stdint.h>
#include <math.h>

#define NND 4096
#define F_IND 1433
#define KP2 1440
#define HIDD 256
#define EMBD 16
#define KCD 10
#define NNZCAP 512

// ---------------- scratch ------------------------------------------------------
__device__ uint16_t g_xh[(size_t)NND * KP2];        // bf16 hi of padded x
__device__ uint16_t g_xl[(size_t)NND * KP2];        // bf16 lo
__device__ uint16_t g_w1h[(size_t)HIDD * KP2];      // bf16 hi of W1^T [256][1440]
__device__ uint16_t g_w1l[(size_t)HIDD * KP2];
__device__ float g_h1[(size_t)NND * HIDD];
__device__ float g_h1o[(size_t)NND * HIDD];
__device__ float g_h2[(size_t)NND * EMBD];
__device__ float g_h2o[(size_t)NND * EMBD];
__device__ float g_s[NND];
__device__ float g_n[NND];
__device__ int   g_nidx[(size_t)NND * NNZCAP];
__device__ int   g_ncnt[NND];

// ---------------- reductions ----------------
__device__ __forceinline__ float warp_red_sum(float v) {
    #pragma unroll
    for (int o = 16; o; o >>= 1) v += __shfl_xor_sync(0xffffffffu, v, o);
    return v;
}
__device__ __forceinline__ float warp_red_max(float v) {
    #pragma unroll
    for (int o = 16; o; o >>= 1) v = fmaxf(v, __shfl_xor_sync(0xffffffffu, v, o));
    return v;
}

// ---------------- bf16 hi/lo split --------------------------------------------
__device__ __forceinline__ void bf16_split(float v, uint16_t& hi, uint16_t& lo) {
    uint32_t u = __float_as_uint(v);
    hi = (uint16_t)(u >> 16);                                  // truncated bf16
    float hf = __uint_as_float(u & 0xFFFF0000u);
    float r = v - hf;                                          // exact
    lo = (uint16_t)(__float_as_uint(__uint_as_float(
             (uint32_t)__float_as_uint(r))) >> 16);            // placeholder (overwritten below)
    // round-to-nearest bf16 of residual:
    uint32_t ru = __float_as_uint(r);
    uint32_t rounded = ru + 0x7FFFu + ((ru >> 16) & 1u);
    lo = (uint16_t)(rounded >> 16);
}

// ================= split-bf16 (3-term) tensor GEMM: h1 = x @ W1 ===============
// A: [4096,1440] bf16 hi/lo, B(=W1^T): [256,1440] bf16 hi/lo (k-contiguous both)
// C: [4096,256] fp32.  CTA 128x64, 8 warps, BK=32, 3-stage cp.async.
// Also accumulates s[row] += h.a_self, n[row] += h.a_neigh via atomics.
#define BM 128
#define BN 64
#define BKT 32
#define STAGES 3
#define ALD2 40
#define BLD2 40
#define S_AH 0
#define S_AL (128 * ALD2)
#define S_BH (2 * 128 * ALD2)
#define S_BL (2 * 128 * ALD2 + 64 * BLD2)
#define STAGE_UNITS (2 * 128 * ALD2 + 2 * 64 * BLD2)
#define GEMM_SMEM_BYTES (STAGES * STAGE_UNITS * 2)

__device__ __forceinline__ void cp_commit() {
    asm volatile("cp.async.commit_group;\n" ::: "memory");
}
template <int N>
__device__ __forceinline__ void cp_wait() {
    asm volatile("cp.async.wait_group %0;\n" :: "n"(N) : "memory");
}
__device__ __forceinline__ void cp16(uint32_t saddr, const void* gaddr) {
    asm volatile("cp.async.cg.shared.global [%0], [%1], 16;\n"
                 :: "r"(saddr), "l"(gaddr) : "memory");
}
__device__ __forceinline__ void mma16(float* d, const uint32_t* a, const uint32_t* b) {
    asm volatile(
        "mma.sync.aligned.m16n8k16.row.col.f32.bf16.bf16.f32 "
        "{%0,%1,%2,%3}, {%4,%5,%6,%7}, {%8,%9}, {%0,%1,%2,%3};\n"
        : "+f"(d[0]), "+f"(d[1]), "+f"(d[2]), "+f"(d[3])
        : "r"(a[0]), "r"(a[1]), "r"(a[2]), "r"(a[3]), "r"(b[0]), "r"(b[1]));
}

__global__ __launch_bounds__(256) void mma_gemm_bf3(
    const uint16_t* __restrict__ Ah, const uint16_t* __restrict__ Al,
    const uint16_t* __restrict__ Bh, const uint16_t* __restrict__ Bl,
    const float* __restrict__ a_self, const float* __restrict__ a_neigh,
    float* __restrict__ C, float* __restrict__ s, float* __restrict__ n)
{
    extern __shared__ uint16_t smem16[];
    const uint32_t sm0 = (uint32_t)__cvta_generic_to_shared(smem16);

    const int tid = threadIdx.x;
    const int m0 = blockIdx.y * BM;
    const int n0 = blockIdx.x * BN;
    const int lane = tid & 31, wid = tid >> 5;
    const int wm = (wid >> 2) * 64;
    const int wn = (wid & 3) * 16;
    const int lr = lane >> 2;
    const int lc = lane & 3;

    float acc[4][2][4];
    #pragma unroll
    for (int i = 0; i < 4; i++)
        #pragma unroll
        for (int j = 0; j < 2; j++)
            #pragma unroll
            for (int e = 0; e < 4; e++) acc[i][j][e] = 0.f;

    auto load_tile = [&](int st, int k0) {
        uint32_t base = sm0 + (uint32_t)(st * STAGE_UNITS) * 2;
        #pragma unroll
        for (int j = 0; j < 2; j++) {
            int q = tid + 256 * j;       // 0..511 : A rows*4 chunks
            int r = q >> 2, c = q & 3;
            cp16(base + (uint32_t)(S_AH + r * ALD2 + c * 8) * 2,
                 Ah + (size_t)(m0 + r) * KP2 + k0 + c * 8);
            cp16(base + (uint32_t)(S_AL + r * ALD2 + c * 8) * 2,
                 Al + (size_t)(m0 + r) * KP2 + k0 + c * 8);
        }
        {
            int r = tid >> 2, c = tid & 3;   // 64 rows * 4 chunks
            cp16(base + (uint32_t)(S_BH + r * BLD2 + c * 8) * 2,
                 Bh + (size_t)(n0 + r) * KP2 + k0 + c * 8);
            cp16(base + (uint32_t)(S_BL + r * BLD2 + c * 8) * 2,
                 Bl + (size_t)(n0 + r) * KP2 + k0 + c * 8);
        }
    };

    const int Ktiles = KP2 / BKT;  // 45
    load_tile(0, 0); cp_commit();
    load_tile(1, BKT); cp_commit();

    for (int it = 0; it < Ktiles; ++it) {
        if (it + 1 < Ktiles) cp_wait<1>(); else cp_wait<0>();
        __syncthreads();
        if (it + 2 < Ktiles) { load_tile((it + 2) % STAGES, (it + 2) * BKT); cp_commit(); }

        const uint16_t* sAh = smem16 + (it % STAGES) * STAGE_UNITS + S_AH;
        const uint16_t* sAl = smem16 + (it % STAGES) * STAGE_UNITS + S_AL;
        const uint16_t* sBh = smem16 + (it % STAGES) * STAGE_UNITS + S_BH;
        const uint16_t* sBl = smem16 + (it % STAGES) * STAGE_UNITS + S_BL;

        #pragma unroll
        for (int kk = 0; kk < BKT; kk += 16) {
            uint32_t bh[2][2], bl[2][2];
            #pragma unroll
            for (int j = 0; j < 2; j++) {
                const uint16_t* pbh = sBh + (wn + 8 * j + lr) * BLD2 + kk + 2 * lc;
                const uint16_t* pbl = sBl + (wn + 8 * j + lr) * BLD2 + kk + 2 * lc;
                bh[j][0] = *(const uint32_t*)pbh;
                bh[j][1] = *(const uint32_t*)(pbh + 8);
                bl[j][0] = *(const uint32_t*)pbl;
                bl[j][1] = *(const uint32_t*)(pbl + 8);
            }
            #pragma unroll
            for (int i = 0; i < 4; i++) {
                const uint16_t* pah = sAh + (wm + 16 * i + lr) * ALD2 + kk + 2 * lc;
                const uint16_t* pal = sAl + (wm + 16 * i + lr) * ALD2 + kk + 2 * lc;
                uint32_t ah[4], al[4];
                ah[0] = *(const uint32_t*)pah;
                ah[1] = *(const uint32_t*)(pah + 8 * ALD2);
                ah[2] = *(const uint32_t*)(pah + 8);
                ah[3] = *(const uint32_t*)(pah + 8 * ALD2 + 8);
                al[0] = *(const uint32_t*)pal;
                al[1] = *(const uint32_t*)(pal + 8 * ALD2);
                al[2] = *(const uint32_t*)(pal + 8);
                al[3] = *(const uint32_t*)(pal + 8 * ALD2 + 8);
                #pragma unroll
                for (int j = 0; j < 2; j++) {
                    mma16(acc[i][j], ah, bh[j]);
                    mma16(acc[i][j], ah, bl[j]);
                    mma16(acc[i][j], al, bh[j]);
                }
            }
        }
        __syncthreads();
    }

    // epilogue: store C + fused partial row-dots with a_self / a_neigh
    float asv[2][2], anv[2][2];
    #pragma unroll
    for (int j = 0; j < 2; j++) {
        int c0 = n0 + wn + 8 * j + 2 * lc;
        asv[j][0] = a_self[c0];     asv[j][1] = a_self[c0 + 1];
        anv[j][0] = a_neigh[c0];    anv[j][1] = a_neigh[c0 + 1];
    }
    #pragma unroll
    for (int i = 0; i < 4; i++) {
        int r0 = m0 + wm + 16 * i + lr;
        float ps0 = 0.f, ps1 = 0.f, pn0 = 0.f, pn1 = 0.f;
        #pragma unroll
        for (int j = 0; j < 2; j++) {
            int c0 = n0 + wn + 8 * j + 2 * lc;
            *reinterpret_cast<float2*>(&C[(size_t)r0 * 256 + c0]) =
                make_float2(acc[i][j][0], acc[i][j][1]);
            *reinterpret_cast<float2*>(&C[(size_t)(r0 + 8) * 256 + c0]) =
                make_float2(acc[i][j][2], acc[i][j][3]);
            ps0 += acc[i][j][0] * asv[j][0] + acc[i][j][1] * asv[j][1];
            pn0 += acc[i][j][0] * anv[j][0] + acc[i][j][1] * anv[j][1];
            ps1 += acc[i][j][2] * asv[j][0] + acc[i][j][3] * asv[j][1];
            pn1 += acc[i][j][2] * anv[j][0] + acc[i][j][3] * anv[j][1];
        }
        // quad reduce (lanes lc 0..3 share a row)
        #pragma unroll
        for (int o = 1; o < 4; o <<= 1) {
            ps0 += __shfl_xor_sync(0xffffffffu, ps0, o);
            pn0 += __shfl_xor_sync(0xffffffffu, pn0, o);
            ps1 += __shfl_xor_sync(0xffffffffu, ps1, o);
            pn1 += __shfl_xor_sync(0xffffffffu, pn1, o);
        }
        if (lc == 0) {
            atomicAdd(&s[r0], ps0);     atomicAdd(&n[r0], pn0);
            atomicAdd(&s[r0 + 8], ps1); atomicAdd(&n[r0 + 8], pn1);
        }
    }
}

// ---------------- split x -> bf16 hi/lo (padded), also zero s,n ----------------
__global__ __launch_bounds__(256) void split_x_kernel(
    const float* __restrict__ x, uint16_t* __restrict__ xh, uint16_t* __restrict__ xl,
    float* __restrict__ s, float* __restrict__ n)
{
    int idx = blockIdx.x * 256 + threadIdx.x;
    if (idx < NND) { s[idx] = 0.f; n[idx] = 0.f; }
    if (idx >= NND * KP2) return;
    int r = idx / KP2, c = idx - r * KP2;
    float v = (c < F_IND) ? x[(size_t)r * F_IND + c] : 0.f;
    uint16_t hi, lo;
    bf16_split(v, hi, lo);
    xh[idx] = hi; xl[idx] = lo;
}

// ---------------- split + transpose W1 -> [256][1440] bf16 hi/lo ---------------
__global__ __launch_bounds__(256) void split_w1_kernel(
    const float* __restrict__ W1, uint16_t* __restrict__ wh, uint16_t* __restrict__ wl)
{
    int idx = blockIdx.x * 256 + threadIdx.x;
    if (idx >= HIDD * KP2) return;
    int nn = idx / KP2, k = idx - nn * KP2;
    float v = (k < F_IND) ? W1[(size_t)k * HIDD + nn] : 0.f;
    uint16_t hi, lo;
    bf16_split(v, hi, lo);
    wh[idx] = hi; wl[idx] = lo;
}

// ---------------- CSR adjacency build -----------------------------------------
__global__ __launch_bounds__(256) void build_csr(
    const float* __restrict__ adj, int* __restrict__ nidx, int* __restrict__ ncnt)
{
    __shared__ int cnt;
    int row = blockIdx.x;
    if (threadIdx.x == 0) cnt = 0;
    __syncthreads();
    const float4* Ar = reinterpret_cast<const float4*>(adj + (size_t)row * NND);
    for (int j4 = threadIdx.x; j4 < NND / 4; j4 += 256) {
        float4 v = Ar[j4];
        if (v.x > 0.f) { int p = atomicAdd(&cnt, 1); if (p < NNZCAP) nidx[(size_t)row * NNZCAP + p] = j4 * 4; }
        if (v.y > 0.f) { int p = atomicAdd(&cnt, 1); if (p < NNZCAP) nidx[(size_t)row * NNZCAP + p] = j4 * 4 + 1; }
        if (v.z > 0.f) { int p = atomicAdd(&cnt, 1); if (p < NNZCAP) nidx[(size_t)row * NNZCAP + p] = j4 * 4 + 2; }
        if (v.w > 0.f) { int p = atomicAdd(&cnt, 1); if (p < NNZCAP) nidx[(size_t)row * NNZCAP + p] = j4 * 4 + 3; }
    }
    __syncthreads();
    if (threadIdx.x == 0) ncnt[row] = min(cnt, NNZCAP);
}

// ---- fused sparse softmax + SpMM, D=256 --------------------------------------
__global__ __launch_bounds__(256) void sparse_att_h256(
    const float* __restrict__ s, const float* __restrict__ n,
    const float* __restrict__ Mm, const float* __restrict__ h,
    const int* __restrict__ nidx, const int* __restrict__ ncnt,
    float* __restrict__ out)
{
    __shared__ int sidx[NNZCAP];
    __shared__ float slog[NNZCAP];
    __shared__ float red[8];
    int row = blockIdx.x, tid = threadIdx.x;
    int cnt = ncnt[row];
    float si = s[row];
    const float* Mr = Mm + (size_t)row * NND;
    const int* Ir = nidx + (size_t)row * NNZCAP;

    float lmax = -INFINITY;
    for (int t = tid; t < cnt; t += 256) {
        int j = Ir[t];
        sidx[t] = j;
        float l = (si + n[j]) * Mr[j];
        l = (l >= 0.f) ? l : 0.2f * l;
        slog[t] = l;
        lmax = fmaxf(lmax, l);
    }
    lmax = warp_red_max(lmax);
    if ((tid & 31) == 0) red[tid >> 5] = lmax;
    __syncthreads();
    if (tid < 32) {
        float v = (tid < 8) ? red[tid] : -INFINITY;
        v = warp_red_max(v);
        if (tid == 0) red[0] = v;
    }
    __syncthreads();
    lmax = red[0];
    __syncthreads();
    float lsum = 0.f;
    for (int t = tid; t < cnt; t += 256) {
        float e = __expf(slog[t] - lmax);
        slog[t] = e;
        lsum += e;
    }
    lsum = warp_red_sum(lsum);
    if ((tid & 31) == 0) red[tid >> 5] = lsum;
    __syncthreads();
    if (tid < 32) {
        float v = (tid < 8) ? red[tid] : 0.f;
        v = warp_red_sum(v);
        if (tid == 0) red[0] = v;
    }
    __syncthreads();
    float inv = 1.f / red[0];

    float acc = 0.f;
    int t = 0;
    for (; t + 4 <= cnt; t += 4) {
        float a0 = slog[t],     a1 = slog[t + 1];
        float a2 = slog[t + 2], a3 = slog[t + 3];
        acc += a0 * h[(size_t)sidx[t] * 256 + tid]
             + a1 * h[(size_t)sidx[t + 1] * 256 + tid]
             + a2 * h[(size_t)sidx[t + 2] * 256 + tid]
             + a3 * h[(size_t)sidx[t + 3] * 256 + tid];
    }
    for (; t < cnt; t++) acc += slog[t] * h[(size_t)sidx[t] * 256 + tid];
    acc *= inv;
    out[(size_t)row * 256 + tid] = (acc > 0.f) ? acc : expm1f(acc);
}

// ---- fused sparse softmax + SpMM, D=16 ---------------------------------------
__global__ __launch_bounds__(128) void sparse_att_h16(
    const float* __restrict__ s, const float* __restrict__ n,
    const float* __restrict__ Mm, const float* __restrict__ h,
    const int* __restrict__ nidx, const int* __restrict__ ncnt,
    float* __restrict__ out)
{
    __shared__ int sidx[NNZCAP];
    __shared__ float slog[NNZCAP];
    __shared__ float red[4];
    __shared__ float part[8][16];
    int row = blockIdx.x, tid = threadIdx.x;
    int cnt = ncnt[row];
    float si = s[row];
    const float* Mr = Mm + (size_t)row * NND;
    const int* Ir = nidx + (size_t)row * NNZCAP;

    float lmax = -INFINITY;
    for (int t = tid; t < cnt; t += 128) {
        int j = Ir[t];
        sidx[t] = j;
        float l = (si + n[j]) * Mr[j];
        l = (l >= 0.f) ? l : 0.2f * l;
        slog[t] = l;
        lmax = fmaxf(lmax, l);
    }
    lmax = warp_red_max(lmax);
    if ((tid & 31) == 0) red[tid >> 5] = lmax;
    __syncthreads();
    if (tid < 32) {
        float v = (tid < 4) ? red[tid] : -INFINITY;
        v = warp_red_max(v);
        if (tid == 0) red[0] = v;
    }
    __syncthreads();
    lmax = red[0];
    __syncthreads();
    float lsum = 0.f;
    for (int t = tid; t < cnt; t += 128) {
        float e = __expf(slog[t] - lmax);
        slog[t] = e;
        lsum += e;
    }
    lsum = warp_red_sum(lsum);
    if ((tid & 31) == 0) red[tid >> 5] = lsum;
    __syncthreads();
    if (tid < 32) {
        float v = (tid < 4) ? red[tid] : 0.f;
        v = warp_red_sum(v);
        if (tid == 0) red[0] = v;
    }
    __syncthreads();
    float inv = 1.f / red[0];

    int p = tid >> 4, d = tid & 15;
    float acc = 0.f;
    for (int t = p; t < cnt; t += 8)
        acc += slog[t] * h[(size_t)sidx[t] * 16 + d];
    part[p][d] = acc;
    __syncthreads();
    if (tid < 16) {
        float a = 0.f;
        #pragma unroll
        for (int pp = 0; pp < 8; pp++) a += part[pp][tid];
        a *= inv;
        out[(size_t)row * 16 + tid] = (a > 0.f) ? a : expm1f(a);
    }
}

// ---------------- GEMM N=16 (h1o @ W2) + fused rowvec16 -----------------------
__global__ __launch_bounds__(256) void gemm_n16_rv(
    const float* __restrict__ A, const float* __restrict__ B, float* __restrict__ C,
    const float* __restrict__ a_self, const float* __restrict__ a_neigh,
    float* __restrict__ s, float* __restrict__ n)
{
    __shared__ float Bs[256][16];
    int tid = threadIdx.x;
    int r = tid >> 4;
    int c = tid & 15;
    int row = blockIdx.x * 16 + r;
    const float* Arow = A + (size_t)row * HIDD;
    float acc = 0.f;

    #pragma unroll
    for (int i = tid; i < 256 * 16; i += 256)
        Bs[i >> 4][i & 15] = B[i];
    __syncthreads();
    #pragma unroll 8
    for (int kk = 0; kk < HIDD; kk += 4) {
        float4 a = *reinterpret_cast<const float4*>(Arow + kk);
        acc += a.x * Bs[kk][c] + a.y * Bs[kk + 1][c]
             + a.z * Bs[kk + 2][c] + a.w * Bs[kk + 3][c];
    }
    C[(size_t)row * 16 + c] = acc;
    // fused s,n: reduce acc * a_self/[a_neigh] over 16 lanes of this row
    float ps = acc * a_self[c];
    float pn = acc * a_neigh[c];
    #pragma unroll
    for (int o = 8; o; o >>= 1) {
        ps += __shfl_xor_sync(0xffffffffu, ps, o);
        pn += __shfl_xor_sync(0xffffffffu, pn, o);
    }
    if (c == 0) { s[row] = ps; n[row] = pn; }
}

// ---------------- normalize z + Student-t q (fused) ---------------------------
__global__ __launch_bounds__(256) void norm_q_kernel(
    const float* __restrict__ h, const float* __restrict__ clusters,
    float* __restrict__ z, float* __restrict__ q)
{
    __shared__ float zs[16][17];
    int tid = threadIdx.x;
    int r = tid >> 4, d = tid & 15;
    int row = blockIdx.x * 16 + r;
    float v = h[(size_t)row * 16 + d];
    float ss = v * v;
    #pragma unroll
    for (int o = 8; o; o >>= 1) ss += __shfl_xor_sync(0xffffffffu, ss, o);
    float zv = v / fmaxf(sqrtf(ss), 1e-12f);
    z[(size_t)row * 16 + d] = zv;
    zs[r][d] = zv;
    __syncthreads();
    if (tid < 160) {
        int rr = tid / 10, k = tid - rr * 10;
        float d2 = 0.f;
        #pragma unroll
        for (int dd = 0; dd < 16; dd++) {
            float df = zs[rr][dd] - clusters[k * 16 + dd];
            d2 += df * df;
        }
        float qk = 1.f / (1.f + d2);
        // normalize across k: need row sum; compute via second pass in smem
        zs[rr][16] = 0.f;   // unused slot guard
        q[(size_t)(blockIdx.x * 16 + rr) * KCD + k] = qk;   // store unnormalized
    }
    __syncthreads();
    // normalize q rows: 16 rows, thread r<16 handles one row
    if (tid < 16) {
        float* qr = &q[(size_t)(blockIdx.x * 16 + tid) * KCD];
        float sum = 0.f;
        #pragma unroll
        for (int k = 0; k < KCD; k++) sum += qr[k];
        float inv = 1.f / sum;
        #pragma unroll
        for (int k = 0; k < KCD; k++) qr[k] *= inv;
    }
}

// ---------------- A_pred = sigmoid(z z^T) -------------------------------------
__global__ __launch_bounds__(256) void a_pred_kernel(
    const float* __restrict__ z, float* __restrict__ out)
{
    __shared__ float zi[64][17];
    __shared__ float zj[64][17];
    int bi = blockIdx.y * 64, bj = blockIdx.x * 64;
    for (int i = threadIdx.x; i < 64 * 16; i += 256) {
        int r = i >> 4, c = i & 15;
        zi[r][c] = z[(size_t)(bi + r) * 16 + c];
        zj[r][c] = z[(size_t)(bj + r) * 16 + c];
    }
    __syncthreads();
    int tr = (threadIdx.x >> 4) << 2;
    int tc = (threadIdx.x & 15) << 2;
    float acc[4][4];
    #pragma unroll
    for (int i = 0; i < 4; i++)
        #pragma unroll
        for (int j = 0; j < 4; j++) acc[i][j] = 0.f;
    #pragma unroll
    for (int k = 0; k < 16; k++) {
        float ri[4], rj[4];
        #pragma unroll
        for (int i = 0; i < 4; i++) ri[i] = zi[tr + i][k];
        #pragma unroll
        for (int j = 0; j < 4; j++) rj[j] = zj[tc + j][k];
        #pragma unroll
        for (int i = 0; i < 4; i++)
            #pragma unroll
            for (int j = 0; j < 4; j++) acc[i][j] += ri[i] * rj[j];
    }
    #pragma unroll
    for (int i = 0; i < 4; i++) {
        float4 v;
        v.x = 1.f / (1.f + __expf(-acc[i][0]));
        v.y = 1.f / (1.f + __expf(-acc[i][1]));
        v.z = 1.f / (1.f + __expf(-acc[i][2]));
        v.w = 1.f / (1.f + __expf(-acc[i][3]));
        *reinterpret_cast<float4*>(&out[(size_t)(bi + tr + i) * NND + bj + tc]) = v;
    }
}

// ---------------- launch ------------------------------------------------------
extern "C" void kernel_launch(void* const* d_in, const int* in_sizes, int n_in,
                              void* d_out, int out_size)
{
    const float* x        = (const float*)d_in[0];
    const float* adj      = (const float*)d_in[1];
    const float* Mm       = (const float*)d_in[2];
    const float* W1       = (const float*)d_in[3];
    const float* a_self1  = (const float*)d_in[4];
    const float* a_neigh1 = (const float*)d_in[5];
    const float* W2       = (const float*)d_in[6];
    const float* a_self2  = (const float*)d_in[7];
    const float* a_neigh2 = (const float*)d_in[8];
    const float* clusters = (const float*)d_in[9];

    float* out    = (float*)d_out;
    float* A_pred = out;
    float* z      = out + (size_t)NND * NND;
    float* q      = z + (size_t)NND * EMBD;

    float *h1, *h1o, *h2, *h2o, *s, *n;
    uint16_t *xh, *xl, *w1h, *w1l;
    int *nidx, *ncnt;
    cudaGetSymbolAddress((void**)&h1,   g_h1);
    cudaGetSymbolAddress((void**)&h1o,  g_h1o);
    cudaGetSymbolAddress((void**)&h2,   g_h2);
    cudaGetSymbolAddress((void**)&h2o,  g_h2o);
    cudaGetSymbolAddress((void**)&s,    g_s);
    cudaGetSymbolAddress((void**)&n,    g_n);
    cudaGetSymbolAddress((void**)&xh,   g_xh);
    cudaGetSymbolAddress((void**)&xl,   g_xl);
    cudaGetSymbolAddress((void**)&w1h,  g_w1h);
    cudaGetSymbolAddress((void**)&w1l,  g_w1l);
    cudaGetSymbolAddress((void**)&nidx, g_nidx);
    cudaGetSymbolAddress((void**)&ncnt, g_ncnt);

    static cudaStream_t s1 = nullptr;
    static cudaEvent_t evF = nullptr, evC = nullptr;
    static bool cfgd = false;
    if (!cfgd) {
        cudaStreamCreateWithFlags(&s1, cudaStreamNonBlocking);
        cudaEventCreateWithFlags(&evF, cudaEventDisableTiming);
        cudaEventCreateWithFlags(&evC, cudaEventDisableTiming);
        cudaFuncSetAttribute(mma_gemm_bf3,
            cudaFuncAttributeMaxDynamicSharedMemorySize, GEMM_SMEM_BYTES);
        cfgd = true;
    }

    // fork: build_csr on side stream, GEMM chain on main stream
    cudaEventRecord(evF, 0);
    cudaStreamWaitEvent(s1, evF, 0);
    build_csr<<<NND, 256, 0, s1>>>(adj, nidx, ncnt);
    cudaEventRecord(evC, s1);

    split_x_kernel<<<(NND * KP2 + 255) / 256, 256>>>(x, xh, xl, s, n);
    split_w1_kernel<<<(HIDD * KP2 + 255) / 256, 256>>>(W1, w1h, w1l);
    mma_gemm_bf3<<<dim3(4, 32), 256, GEMM_SMEM_BYTES>>>(
        xh, xl, w1h, w1l, a_self1, a_neigh1, h1, s, n);

    // join
    cudaStreamWaitEvent(0, evC, 0);
    sparse_att_h256<<<NND, 256>>>(s, n, Mm, h1, nidx, ncnt, h1o);

    // Layer 2
    gemm_n16_rv<<<NND / 16, 256>>>(h1o, W2, h2, a_self2, a_neigh2, s, n);
    sparse_att_h16<<<NND, 128>>>(s, n, Mm, h2, nidx, ncnt, h2o);

    // Outputs
    norm_q_kernel<<<NND / 16, 256>>>(h2o, clusters, z, q);
    a_pred_kernel<<<dim3(64, 64), 256>>>(z, A_pred);
}

// round 7
// speedup vs baseline: 9.4515x; 1.0521x over previous
#include <cuda_runtime.h>
#include <stdint.h>
#include <math.h>

#define NND 4096
#define F_IND 1433
#define KP2 1440
#define HIDD 256
#define EMBD 16
#define KCD 10
#define NNZCAP 512

// ---------------- scratch ------------------------------------------------------
__device__ uint16_t g_xh[(size_t)NND * KP2];
__device__ uint16_t g_xl[(size_t)NND * KP2];
__device__ uint16_t g_w1h[(size_t)HIDD * KP2];
__device__ uint16_t g_w1l[(size_t)HIDD * KP2];
__device__ float g_h1[(size_t)NND * HIDD];
__device__ float g_h1o[(size_t)NND * HIDD];
__device__ float g_h2[(size_t)NND * EMBD];
__device__ float g_h2o[(size_t)NND * EMBD];
__device__ float g_s[NND];
__device__ float g_n[NND];
__device__ int   g_nidx[(size_t)NND * NNZCAP];
__device__ int   g_ncnt[NND];

// ---------------- reductions ----------------
__device__ __forceinline__ float warp_red_sum(float v) {
    #pragma unroll
    for (int o = 16; o; o >>= 1) v += __shfl_xor_sync(0xffffffffu, v, o);
    return v;
}
__device__ __forceinline__ float warp_red_max(float v) {
    #pragma unroll
    for (int o = 16; o; o >>= 1) v = fmaxf(v, __shfl_xor_sync(0xffffffffu, v, o));
    return v;
}

// ---------------- bf16 hi/lo split --------------------------------------------
__device__ __forceinline__ void bf16_split(float v, uint16_t& hi, uint16_t& lo) {
    uint32_t u = __float_as_uint(v);
    hi = (uint16_t)(u >> 16);                       // truncated bf16
    float hf = __uint_as_float(u & 0xFFFF0000u);
    float r = v - hf;                               // exact residual
    uint32_t ru = __float_as_uint(r);
    uint32_t rounded = ru + 0x7FFFu + ((ru >> 16) & 1u);
    lo = (uint16_t)(rounded >> 16);
}

// ================= split-bf16 (3-term) tensor GEMM, split-K=2 =================
// h1 = x @ W1 with A,B pre-split to bf16 hi/lo.  CTA tile 128x64, BK=32,
// 3-stage cp.async, grid (4,32,2): z halves the K range; partials atomicAdd'd.
// Epilogue also accumulates s = h1.a_self, n = h1.a_neigh (linear in C).
#define BM 128
#define BN 64
#define BKT 32
#define STAGES 3
#define ALD2 40
#define BLD2 40
#define S_AH 0
#define S_AL (128 * ALD2)
#define S_BH (2 * 128 * ALD2)
#define S_BL (2 * 128 * ALD2 + 64 * BLD2)
#define STAGE_UNITS (2 * 128 * ALD2 + 2 * 64 * BLD2)
#define GEMM_SMEM_BYTES (STAGES * STAGE_UNITS * 2)
#define KTILES_Z0 23
#define KTILES_Z1 22

__device__ __forceinline__ void cp_commit() {
    asm volatile("cp.async.commit_group;\n" ::: "memory");
}
template <int N>
__device__ __forceinline__ void cp_wait() {
    asm volatile("cp.async.wait_group %0;\n" :: "n"(N) : "memory");
}
__device__ __forceinline__ void cp16(uint32_t saddr, const void* gaddr) {
    asm volatile("cp.async.cg.shared.global [%0], [%1], 16;\n"
                 :: "r"(saddr), "l"(gaddr) : "memory");
}
__device__ __forceinline__ void mma16(float* d, const uint32_t* a, const uint32_t* b) {
    asm volatile(
        "mma.sync.aligned.m16n8k16.row.col.f32.bf16.bf16.f32 "
        "{%0,%1,%2,%3}, {%4,%5,%6,%7}, {%8,%9}, {%0,%1,%2,%3};\n"
        : "+f"(d[0]), "+f"(d[1]), "+f"(d[2]), "+f"(d[3])
        : "r"(a[0]), "r"(a[1]), "r"(a[2]), "r"(a[3]), "r"(b[0]), "r"(b[1]));
}

__global__ __launch_bounds__(256, 2) void mma_gemm_bf3(
    const uint16_t* __restrict__ Ah, const uint16_t* __restrict__ Al,
    const uint16_t* __restrict__ Bh, const uint16_t* __restrict__ Bl,
    const float* __restrict__ a_self, const float* __restrict__ a_neigh,
    float* __restrict__ C, float* __restrict__ s, float* __restrict__ n)
{
    extern __shared__ uint16_t smem16[];
    const uint32_t sm0 = (uint32_t)__cvta_generic_to_shared(smem16);

    const int tid = threadIdx.x;
    const int m0 = blockIdx.y * BM;
    const int n0 = blockIdx.x * BN;
    const int zz = blockIdx.z;
    const int kbase = zz * (KTILES_Z0 * BKT);
    const int Ktiles = zz ? KTILES_Z1 : KTILES_Z0;

    const int lane = tid & 31, wid = tid >> 5;
    const int wm = (wid >> 2) * 64;
    const int wn = (wid & 3) * 16;
    const int lr = lane >> 2;
    const int lc = lane & 3;

    float acc[4][2][4];
    #pragma unroll
    for (int i = 0; i < 4; i++)
        #pragma unroll
        for (int j = 0; j < 2; j++)
            #pragma unroll
            for (int e = 0; e < 4; e++) acc[i][j][e] = 0.f;

    auto load_tile = [&](int st, int k0) {
        uint32_t base = sm0 + (uint32_t)(st * STAGE_UNITS) * 2;
        #pragma unroll
        for (int j = 0; j < 2; j++) {
            int q = tid + 256 * j;
            int r = q >> 2, c = q & 3;
            cp16(base + (uint32_t)(S_AH + r * ALD2 + c * 8) * 2,
                 Ah + (size_t)(m0 + r) * KP2 + k0 + c * 8);
            cp16(base + (uint32_t)(S_AL + r * ALD2 + c * 8) * 2,
                 Al + (size_t)(m0 + r) * KP2 + k0 + c * 8);
        }
        {
            int r = tid >> 2, c = tid & 3;
            cp16(base + (uint32_t)(S_BH + r * BLD2 + c * 8) * 2,
                 Bh + (size_t)(n0 + r) * KP2 + k0 + c * 8);
            cp16(base + (uint32_t)(S_BL + r * BLD2 + c * 8) * 2,
                 Bl + (size_t)(n0 + r) * KP2 + k0 + c * 8);
        }
    };

    load_tile(0, kbase); cp_commit();
    load_tile(1, kbase + BKT); cp_commit();

    for (int it = 0; it < Ktiles; ++it) {
        if (it + 1 < Ktiles) cp_wait<1>(); else cp_wait<0>();
        __syncthreads();
        if (it + 2 < Ktiles) {
            load_tile((it + 2) % STAGES, kbase + (it + 2) * BKT);
            cp_commit();
        }

        const uint16_t* sAh = smem16 + (it % STAGES) * STAGE_UNITS + S_AH;
        const uint16_t* sAl = smem16 + (it % STAGES) * STAGE_UNITS + S_AL;
        const uint16_t* sBh = smem16 + (it % STAGES) * STAGE_UNITS + S_BH;
        const uint16_t* sBl = smem16 + (it % STAGES) * STAGE_UNITS + S_BL;

        #pragma unroll
        for (int kk = 0; kk < BKT; kk += 16) {
            uint32_t bh[2][2], bl[2][2];
            #pragma unroll
            for (int j = 0; j < 2; j++) {
                const uint16_t* pbh = sBh + (wn + 8 * j + lr) * BLD2 + kk + 2 * lc;
                const uint16_t* pbl = sBl + (wn + 8 * j + lr) * BLD2 + kk + 2 * lc;
                bh[j][0] = *(const uint32_t*)pbh;
                bh[j][1] = *(const uint32_t*)(pbh + 8);
                bl[j][0] = *(const uint32_t*)pbl;
                bl[j][1] = *(const uint32_t*)(pbl + 8);
            }
            #pragma unroll
            for (int i = 0; i < 4; i++) {
                const uint16_t* pah = sAh + (wm + 16 * i + lr) * ALD2 + kk + 2 * lc;
                const uint16_t* pal = sAl + (wm + 16 * i + lr) * ALD2 + kk + 2 * lc;
                uint32_t ah[4], al[4];
                ah[0] = *(const uint32_t*)pah;
                ah[1] = *(const uint32_t*)(pah + 8 * ALD2);
                ah[2] = *(const uint32_t*)(pah + 8);
                ah[3] = *(const uint32_t*)(pah + 8 * ALD2 + 8);
                al[0] = *(const uint32_t*)pal;
                al[1] = *(const uint32_t*)(pal + 8 * ALD2);
                al[2] = *(const uint32_t*)(pal + 8);
                al[3] = *(const uint32_t*)(pal + 8 * ALD2 + 8);
                #pragma unroll
                for (int j = 0; j < 2; j++) {
                    mma16(acc[i][j], ah, bh[j]);
                    mma16(acc[i][j], ah, bl[j]);
                    mma16(acc[i][j], al, bh[j]);
                }
            }
        }
        __syncthreads();
    }

    // epilogue: atomicAdd partials into C (pre-zeroed) + fused s/n partial dots
    float asv[2][2], anv[2][2];
    #pragma unroll
    for (int j = 0; j < 2; j++) {
        int c0 = n0 + wn + 8 * j + 2 * lc;
        asv[j][0] = a_self[c0];     asv[j][1] = a_self[c0 + 1];
        anv[j][0] = a_neigh[c0];    anv[j][1] = a_neigh[c0 + 1];
    }
    #pragma unroll
    for (int i = 0; i < 4; i++) {
        int r0 = m0 + wm + 16 * i + lr;
        float ps0 = 0.f, ps1 = 0.f, pn0 = 0.f, pn1 = 0.f;
        #pragma unroll
        for (int j = 0; j < 2; j++) {
            int c0 = n0 + wn + 8 * j + 2 * lc;
            atomicAdd(&C[(size_t)r0 * 256 + c0],       acc[i][j][0]);
            atomicAdd(&C[(size_t)r0 * 256 + c0 + 1],   acc[i][j][1]);
            atomicAdd(&C[(size_t)(r0 + 8) * 256 + c0],     acc[i][j][2]);
            atomicAdd(&C[(size_t)(r0 + 8) * 256 + c0 + 1], acc[i][j][3]);
            ps0 += acc[i][j][0] * asv[j][0] + acc[i][j][1] * asv[j][1];
            pn0 += acc[i][j][0] * anv[j][0] + acc[i][j][1] * anv[j][1];
            ps1 += acc[i][j][2] * asv[j][0] + acc[i][j][3] * asv[j][1];
            pn1 += acc[i][j][2] * anv[j][0] + acc[i][j][3] * anv[j][1];
        }
        #pragma unroll
        for (int o = 1; o < 4; o <<= 1) {
            ps0 += __shfl_xor_sync(0xffffffffu, ps0, o);
            pn0 += __shfl_xor_sync(0xffffffffu, pn0, o);
            ps1 += __shfl_xor_sync(0xffffffffu, ps1, o);
            pn1 += __shfl_xor_sync(0xffffffffu, pn1, o);
        }
        if (lc == 0) {
            atomicAdd(&s[r0], ps0);     atomicAdd(&n[r0], pn0);
            atomicAdd(&s[r0 + 8], ps1); atomicAdd(&n[r0 + 8], pn1);
        }
    }
}

// -------- fused prep: split x & W1^T to bf16 hi/lo, zero s/n/h1 ----------------
__global__ __launch_bounds__(256) void split_prep_kernel(
    const float* __restrict__ x, const float* __restrict__ W1,
    uint16_t* __restrict__ xh, uint16_t* __restrict__ xl,
    uint16_t* __restrict__ wh, uint16_t* __restrict__ wl,
    float* __restrict__ s, float* __restrict__ n, float* __restrict__ h1zero)
{
    int idx = blockIdx.x * 256 + threadIdx.x;
    if (idx < NND) { s[idx] = 0.f; n[idx] = 0.f; }
    if (idx < NND * HIDD) h1zero[idx] = 0.f;
    if (idx < NND * KP2) {
        int r = idx / KP2, c = idx - r * KP2;
        float v = (c < F_IND) ? x[(size_t)r * F_IND + c] : 0.f;
        uint16_t hi, lo;
        bf16_split(v, hi, lo);
        xh[idx] = hi; xl[idx] = lo;
    } else {
        int idx2 = idx - NND * KP2;
        if (idx2 < HIDD * KP2) {
            int nn = idx2 / KP2, k = idx2 - nn * KP2;
            float v = (k < F_IND) ? W1[(size_t)k * HIDD + nn] : 0.f;
            uint16_t hi, lo;
            bf16_split(v, hi, lo);
            wh[idx2] = hi; wl[idx2] = lo;
        }
    }
}

// ---------------- CSR adjacency build -----------------------------------------
__global__ __launch_bounds__(256) void build_csr(
    const float* __restrict__ adj, int* __restrict__ nidx, int* __restrict__ ncnt)
{
    __shared__ int cnt;
    int row = blockIdx.x;
    if (threadIdx.x == 0) cnt = 0;
    __syncthreads();
    const float4* Ar = reinterpret_cast<const float4*>(adj + (size_t)row * NND);
    for (int j4 = threadIdx.x; j4 < NND / 4; j4 += 256) {
        float4 v = Ar[j4];
        if (v.x > 0.f) { int p = atomicAdd(&cnt, 1); if (p < NNZCAP) nidx[(size_t)row * NNZCAP + p] = j4 * 4; }
        if (v.y > 0.f) { int p = atomicAdd(&cnt, 1); if (p < NNZCAP) nidx[(size_t)row * NNZCAP + p] = j4 * 4 + 1; }
        if (v.z > 0.f) { int p = atomicAdd(&cnt, 1); if (p < NNZCAP) nidx[(size_t)row * NNZCAP + p] = j4 * 4 + 2; }
        if (v.w > 0.f) { int p = atomicAdd(&cnt, 1); if (p < NNZCAP) nidx[(size_t)row * NNZCAP + p] = j4 * 4 + 3; }
    }
    __syncthreads();
    if (threadIdx.x == 0) ncnt[row] = min(cnt, NNZCAP);
}

// ---- fused sparse softmax + SpMM, D=256 --------------------------------------
__global__ __launch_bounds__(256) void sparse_att_h256(
    const float* __restrict__ s, const float* __restrict__ n,
    const float* __restrict__ Mm, const float* __restrict__ h,
    const int* __restrict__ nidx, const int* __restrict__ ncnt,
    float* __restrict__ out)
{
    __shared__ int sidx[NNZCAP];
    __shared__ float slog[NNZCAP];
    __shared__ float red[8];
    int row = blockIdx.x, tid = threadIdx.x;
    int cnt = ncnt[row];
    float si = s[row];
    const float* Mr = Mm + (size_t)row * NND;
    const int* Ir = nidx + (size_t)row * NNZCAP;

    float lmax = -INFINITY;
    for (int t = tid; t < cnt; t += 256) {
        int j = Ir[t];
        sidx[t] = j;
        float l = (si + n[j]) * Mr[j];
        l = (l >= 0.f) ? l : 0.2f * l;
        slog[t] = l;
        lmax = fmaxf(lmax, l);
    }
    lmax = warp_red_max(lmax);
    if ((tid & 31) == 0) red[tid >> 5] = lmax;
    __syncthreads();
    if (tid < 32) {
        float v = (tid < 8) ? red[tid] : -INFINITY;
        v = warp_red_max(v);
        if (tid == 0) red[0] = v;
    }
    __syncthreads();
    lmax = red[0];
    __syncthreads();
    float lsum = 0.f;
    for (int t = tid; t < cnt; t += 256) {
        float e = __expf(slog[t] - lmax);
        slog[t] = e;
        lsum += e;
    }
    lsum = warp_red_sum(lsum);
    if ((tid & 31) == 0) red[tid >> 5] = lsum;
    __syncthreads();
    if (tid < 32) {
        float v = (tid < 8) ? red[tid] : 0.f;
        v = warp_red_sum(v);
        if (tid == 0) red[0] = v;
    }
    __syncthreads();
    float inv = 1.f / red[0];

    float acc = 0.f;
    int t = 0;
    for (; t + 4 <= cnt; t += 4) {
        float a0 = slog[t],     a1 = slog[t + 1];
        float a2 = slog[t + 2], a3 = slog[t + 3];
        acc += a0 * h[(size_t)sidx[t] * 256 + tid]
             + a1 * h[(size_t)sidx[t + 1] * 256 + tid]
             + a2 * h[(size_t)sidx[t + 2] * 256 + tid]
             + a3 * h[(size_t)sidx[t + 3] * 256 + tid];
    }
    for (; t < cnt; t++) acc += slog[t] * h[(size_t)sidx[t] * 256 + tid];
    acc *= inv;
    out[(size_t)row * 256 + tid] = (acc > 0.f) ? acc : expm1f(acc);
}

// ---- fused sparse softmax + SpMM, D=16 ---------------------------------------
__global__ __launch_bounds__(128) void sparse_att_h16(
    const float* __restrict__ s, const float* __restrict__ n,
    const float* __restrict__ Mm, const float* __restrict__ h,
    const int* __restrict__ nidx, const int* __restrict__ ncnt,
    float* __restrict__ out)
{
    __shared__ int sidx[NNZCAP];
    __shared__ float slog[NNZCAP];
    __shared__ float red[4];
    __shared__ float part[8][16];
    int row = blockIdx.x, tid = threadIdx.x;
    int cnt = ncnt[row];
    float si = s[row];
    const float* Mr = Mm + (size_t)row * NND;
    const int* Ir = nidx + (size_t)row * NNZCAP;

    float lmax = -INFINITY;
    for (int t = tid; t < cnt; t += 128) {
        int j = Ir[t];
        sidx[t] = j;
        float l = (si + n[j]) * Mr[j];
        l = (l >= 0.f) ? l : 0.2f * l;
        slog[t] = l;
        lmax = fmaxf(lmax, l);
    }
    lmax = warp_red_max(lmax);
    if ((tid & 31) == 0) red[tid >> 5] = lmax;
    __syncthreads();
    if (tid < 32) {
        float v = (tid < 4) ? red[tid] : -INFINITY;
        v = warp_red_max(v);
        if (tid == 0) red[0] = v;
    }
    __syncthreads();
    lmax = red[0];
    __syncthreads();
    float lsum = 0.f;
    for (int t = tid; t < cnt; t += 128) {
        float e = __expf(slog[t] - lmax);
        slog[t] = e;
        lsum += e;
    }
    lsum = warp_red_sum(lsum);
    if ((tid & 31) == 0) red[tid >> 5] = lsum;
    __syncthreads();
    if (tid < 32) {
        float v = (tid < 4) ? red[tid] : 0.f;
        v = warp_red_sum(v);
        if (tid == 0) red[0] = v;
    }
    __syncthreads();
    float inv = 1.f / red[0];

    int p = tid >> 4, d = tid & 15;
    float acc = 0.f;
    for (int t = p; t < cnt; t += 8)
        acc += slog[t] * h[(size_t)sidx[t] * 16 + d];
    part[p][d] = acc;
    __syncthreads();
    if (tid < 16) {
        float a = 0.f;
        #pragma unroll
        for (int pp = 0; pp < 8; pp++) a += part[pp][tid];
        a *= inv;
        out[(size_t)row * 16 + tid] = (a > 0.f) ? a : expm1f(a);
    }
}

// ---------------- GEMM N=16 (h1o @ W2) + fused rowvec16 -----------------------
__global__ __launch_bounds__(256) void gemm_n16_rv(
    const float* __restrict__ A, const float* __restrict__ B, float* __restrict__ C,
    const float* __restrict__ a_self, const float* __restrict__ a_neigh,
    float* __restrict__ s, float* __restrict__ n)
{
    __shared__ float Bs[256][16];
    int tid = threadIdx.x;
    int r = tid >> 4;
    int c = tid & 15;
    int row = blockIdx.x * 16 + r;
    const float* Arow = A + (size_t)row * HIDD;
    float acc = 0.f;

    #pragma unroll
    for (int i = tid; i < 256 * 16; i += 256)
        Bs[i >> 4][i & 15] = B[i];
    __syncthreads();
    #pragma unroll 8
    for (int kk = 0; kk < HIDD; kk += 4) {
        float4 a = *reinterpret_cast<const float4*>(Arow + kk);
        acc += a.x * Bs[kk][c] + a.y * Bs[kk + 1][c]
             + a.z * Bs[kk + 2][c] + a.w * Bs[kk + 3][c];
    }
    C[(size_t)row * 16 + c] = acc;
    float ps = acc * a_self[c];
    float pn = acc * a_neigh[c];
    #pragma unroll
    for (int o = 8; o; o >>= 1) {
        ps += __shfl_xor_sync(0xffffffffu, ps, o);
        pn += __shfl_xor_sync(0xffffffffu, pn, o);
    }
    if (c == 0) { s[row] = ps; n[row] = pn; }
}

// ---------------- normalize z + Student-t q (fused) ---------------------------
__global__ __launch_bounds__(256) void norm_q_kernel(
    const float* __restrict__ h, const float* __restrict__ clusters,
    float* __restrict__ z, float* __restrict__ q)
{
    __shared__ float zs[16][17];
    int tid = threadIdx.x;
    int r = tid >> 4, d = tid & 15;
    int row = blockIdx.x * 16 + r;
    float v = h[(size_t)row * 16 + d];
    float ss = v * v;
    #pragma unroll
    for (int o = 8; o; o >>= 1) ss += __shfl_xor_sync(0xffffffffu, ss, o);
    float zv = v / fmaxf(sqrtf(ss), 1e-12f);
    z[(size_t)row * 16 + d] = zv;
    zs[r][d] = zv;
    __syncthreads();
    if (tid < 160) {
        int rr = tid / 10, k = tid - rr * 10;
        float d2 = 0.f;
        #pragma unroll
        for (int dd = 0; dd < 16; dd++) {
            float df = zs[rr][dd] - clusters[k * 16 + dd];
            d2 += df * df;
        }
        q[(size_t)(blockIdx.x * 16 + rr) * KCD + k] = 1.f / (1.f + d2);
    }
    __syncthreads();
    if (tid < 16) {
        float* qr = &q[(size_t)(blockIdx.x * 16 + tid) * KCD];
        float sum = 0.f;
        #pragma unroll
        for (int k = 0; k < KCD; k++) sum += qr[k];
        float inv = 1.f / sum;
        #pragma unroll
        for (int k = 0; k < KCD; k++) qr[k] *= inv;
    }
}

// ---------------- A_pred = sigmoid(z z^T) -------------------------------------
__global__ __launch_bounds__(256) void a_pred_kernel(
    const float* __restrict__ z, float* __restrict__ out)
{
    __shared__ float zi[64][17];
    __shared__ float zj[64][17];
    int bi = blockIdx.y * 64, bj = blockIdx.x * 64;
    for (int i = threadIdx.x; i < 64 * 16; i += 256) {
        int r = i >> 4, c = i & 15;
        zi[r][c] = z[(size_t)(bi + r) * 16 + c];
        zj[r][c] = z[(size_t)(bj + r) * 16 + c];
    }
    __syncthreads();
    int tr = (threadIdx.x >> 4) << 2;
    int tc = (threadIdx.x & 15) << 2;
    float acc[4][4];
    #pragma unroll
    for (int i = 0; i < 4; i++)
        #pragma unroll
        for (int j = 0; j < 4; j++) acc[i][j] = 0.f;
    #pragma unroll
    for (int k = 0; k < 16; k++) {
        float ri[4], rj[4];
        #pragma unroll
        for (int i = 0; i < 4; i++) ri[i] = zi[tr + i][k];
        #pragma unroll
        for (int j = 0; j < 4; j++) rj[j] = zj[tc + j][k];
        #pragma unroll
        for (int i = 0; i < 4; i++)
            #pragma unroll
            for (int j = 0; j < 4; j++) acc[i][j] += ri[i] * rj[j];
    }
    #pragma unroll
    for (int i = 0; i < 4; i++) {
        float4 v;
        v.x = 1.f / (1.f + __expf(-acc[i][0]));
        v.y = 1.f / (1.f + __expf(-acc[i][1]));
        v.z = 1.f / (1.f + __expf(-acc[i][2]));
        v.w = 1.f / (1.f + __expf(-acc[i][3]));
        *reinterpret_cast<float4*>(&out[(size_t)(bi + tr + i) * NND + bj + tc]) = v;
    }
}

// ---------------- launch ------------------------------------------------------
extern "C" void kernel_launch(void* const* d_in, const int* in_sizes, int n_in,
                              void* d_out, int out_size)
{
    const float* x        = (const float*)d_in[0];
    const float* adj      = (const float*)d_in[1];
    const float* Mm       = (const float*)d_in[2];
    const float* W1       = (const float*)d_in[3];
    const float* a_self1  = (const float*)d_in[4];
    const float* a_neigh1 = (const float*)d_in[5];
    const float* W2       = (const float*)d_in[6];
    const float* a_self2  = (const float*)d_in[7];
    const float* a_neigh2 = (const float*)d_in[8];
    const float* clusters = (const float*)d_in[9];

    float* out    = (float*)d_out;
    float* A_pred = out;
    float* z      = out + (size_t)NND * NND;
    float* q      = z + (size_t)NND * EMBD;

    float *h1, *h1o, *h2, *h2o, *s, *n;
    uint16_t *xh, *xl, *w1h, *w1l;
    int *nidx, *ncnt;
    cudaGetSymbolAddress((void**)&h1,   g_h1);
    cudaGetSymbolAddress((void**)&h1o,  g_h1o);
    cudaGetSymbolAddress((void**)&h2,   g_h2);
    cudaGetSymbolAddress((void**)&h2o,  g_h2o);
    cudaGetSymbolAddress((void**)&s,    g_s);
    cudaGetSymbolAddress((void**)&n,    g_n);
    cudaGetSymbolAddress((void**)&xh,   g_xh);
    cudaGetSymbolAddress((void**)&xl,   g_xl);
    cudaGetSymbolAddress((void**)&w1h,  g_w1h);
    cudaGetSymbolAddress((void**)&w1l,  g_w1l);
    cudaGetSymbolAddress((void**)&nidx, g_nidx);
    cudaGetSymbolAddress((void**)&ncnt, g_ncnt);

    static cudaStream_t s1 = nullptr;
    static cudaEvent_t evF = nullptr, evC = nullptr;
    static bool cfgd = false;
    if (!cfgd) {
        cudaStreamCreateWithFlags(&s1, cudaStreamNonBlocking);
        cudaEventCreateWithFlags(&evF, cudaEventDisableTiming);
        cudaEventCreateWithFlags(&evC, cudaEventDisableTiming);
        cudaFuncSetAttribute(mma_gemm_bf3,
            cudaFuncAttributeMaxDynamicSharedMemorySize, GEMM_SMEM_BYTES);
        cfgd = true;
    }

    // fork: build_csr on side stream
    cudaEventRecord(evF, 0);
    cudaStreamWaitEvent(s1, evF, 0);
    build_csr<<<NND, 256, 0, s1>>>(adj, nidx, ncnt);
    cudaEventRecord(evC, s1);

    // prep (split x, W1; zero s/n/h1) then split-K GEMM
    int prep_elems = NND * KP2 + HIDD * KP2;
    split_prep_kernel<<<(prep_elems + 255) / 256, 256>>>(
        x, W1, xh, xl, w1h, w1l, s, n, h1);
    mma_gemm_bf3<<<dim3(4, 32, 2), 256, GEMM_SMEM_BYTES>>>(
        xh, xl, w1h, w1l, a_self1, a_neigh1, h1, s, n);

    // join
    cudaStreamWaitEvent(0, evC, 0);
    sparse_att_h256<<<NND, 256>>>(s, n, Mm, h1, nidx, ncnt, h1o);

    // Layer 2
    gemm_n16_rv<<<NND / 16, 256>>>(h1o, W2, h2, a_self2, a_neigh2, s, n);
    sparse_att_h16<<<NND, 128>>>(s, n, Mm, h2, nidx, ncnt, h2o);

    // Outputs
    norm_q_kernel<<<NND / 16, 256>>>(h2o, clusters, z, q);
    a_pred_kernel<<<dim3(64, 64), 256>>>(z, A_pred);
}

// round 8
// speedup vs baseline: 9.8296x; 1.0400x over previous
#include <cuda_runtime.h>
#include <stdint.h>
#include <math.h>

#define NND 4096
#define F_IND 1433
#define KP2 1440
#define HIDD 256
#define EMBD 16
#define KCD 10
#define NNZCAP 512

// ---------------- scratch ------------------------------------------------------
__device__ uint16_t g_xh[(size_t)NND * KP2];
__device__ uint16_t g_xl[(size_t)NND * KP2];
__device__ uint16_t g_w1h[(size_t)HIDD * KP2];
__device__ uint16_t g_w1l[(size_t)HIDD * KP2];
__device__ float g_h1[(size_t)NND * HIDD];
__device__ float g_h1o[(size_t)NND * HIDD];
__device__ float g_h2[(size_t)NND * EMBD];
__device__ float g_s[NND];
__device__ float g_n[NND];
__device__ int   g_nidx[(size_t)NND * NNZCAP];
__device__ int   g_ncnt[NND];

// ---------------- reductions ----------------
__device__ __forceinline__ float warp_red_sum(float v) {
    #pragma unroll
    for (int o = 16; o; o >>= 1) v += __shfl_xor_sync(0xffffffffu, v, o);
    return v;
}
__device__ __forceinline__ float warp_red_max(float v) {
    #pragma unroll
    for (int o = 16; o; o >>= 1) v = fmaxf(v, __shfl_xor_sync(0xffffffffu, v, o));
    return v;
}

// ---------------- bf16 hi/lo split --------------------------------------------
__device__ __forceinline__ void bf16_split(float v, uint16_t& hi, uint16_t& lo) {
    uint32_t u = __float_as_uint(v);
    hi = (uint16_t)(u >> 16);                       // truncated bf16
    float hf = __uint_as_float(u & 0xFFFF0000u);
    float r = v - hf;                               // exact residual
    uint32_t ru = __float_as_uint(r);
    uint32_t rounded = ru + 0x7FFFu + ((ru >> 16) & 1u);
    lo = (uint16_t)(rounded >> 16);
}

// ================= split-bf16 (3-term) tensor GEMM, split-K=2 =================
#define BM 128
#define BN 64
#define BKT 32
#define STAGES 3
#define ALD2 40
#define BLD2 40
#define S_AH 0
#define S_AL (128 * ALD2)
#define S_BH (2 * 128 * ALD2)
#define S_BL (2 * 128 * ALD2 + 64 * BLD2)
#define STAGE_UNITS (2 * 128 * ALD2 + 2 * 64 * BLD2)
#define GEMM_SMEM_BYTES (STAGES * STAGE_UNITS * 2)
#define KTILES_Z0 23
#define KTILES_Z1 22

__device__ __forceinline__ void cp_commit() {
    asm volatile("cp.async.commit_group;\n" ::: "memory");
}
template <int N>
__device__ __forceinline__ void cp_wait() {
    asm volatile("cp.async.wait_group %0;\n" :: "n"(N) : "memory");
}
__device__ __forceinline__ void cp16(uint32_t saddr, const void* gaddr) {
    asm volatile("cp.async.cg.shared.global [%0], [%1], 16;\n"
                 :: "r"(saddr), "l"(gaddr) : "memory");
}
__device__ __forceinline__ void mma16(float* d, const uint32_t* a, const uint32_t* b) {
    asm volatile(
        "mma.sync.aligned.m16n8k16.row.col.f32.bf16.bf16.f32 "
        "{%0,%1,%2,%3}, {%4,%5,%6,%7}, {%8,%9}, {%0,%1,%2,%3};\n"
        : "+f"(d[0]), "+f"(d[1]), "+f"(d[2]), "+f"(d[3])
        : "r"(a[0]), "r"(a[1]), "r"(a[2]), "r"(a[3]), "r"(b[0]), "r"(b[1]));
}
__device__ __forceinline__ void ldsm_x4(uint32_t* r, uint32_t saddr) {
    asm volatile("ldmatrix.sync.aligned.m8n8.x4.shared.b16 {%0,%1,%2,%3}, [%4];\n"
        : "=r"(r[0]), "=r"(r[1]), "=r"(r[2]), "=r"(r[3]) : "r"(saddr));
}
__device__ __forceinline__ void ldsm_x2(uint32_t* r, uint32_t saddr) {
    asm volatile("ldmatrix.sync.aligned.m8n8.x2.shared.b16 {%0,%1}, [%2];\n"
        : "=r"(r[0]), "=r"(r[1]) : "r"(saddr));
}

__global__ __launch_bounds__(256, 2) void mma_gemm_bf3(
    const uint16_t* __restrict__ Ah, const uint16_t* __restrict__ Al,
    const uint16_t* __restrict__ Bh, const uint16_t* __restrict__ Bl,
    const float* __restrict__ a_self, const float* __restrict__ a_neigh,
    float* __restrict__ C, float* __restrict__ s, float* __restrict__ n)
{
    extern __shared__ uint16_t smem16[];
    const uint32_t sm0 = (uint32_t)__cvta_generic_to_shared(smem16);

    const int tid = threadIdx.x;
    const int m0 = blockIdx.y * BM;
    const int n0 = blockIdx.x * BN;
    const int zz = blockIdx.z;
    const int kbase = zz * (KTILES_Z0 * BKT);
    const int Ktiles = zz ? KTILES_Z1 : KTILES_Z0;

    const int lane = tid & 31, wid = tid >> 5;
    const int wm = (wid >> 2) * 64;
    const int wn = (wid & 3) * 16;
    const int lr = lane >> 2;
    const int lc = lane & 3;

    // ldmatrix per-lane element offsets (uint16 units)
    const int aoff = (wm + (lane & 15)) * ALD2 + (lane >> 4) * 8;
    const int l2 = lane & 15;
    const int boff = (wn + (l2 & 7)) * BLD2 + (l2 >> 3) * 8;

    float acc[4][2][4];
    #pragma unroll
    for (int i = 0; i < 4; i++)
        #pragma unroll
        for (int j = 0; j < 2; j++)
            #pragma unroll
            for (int e = 0; e < 4; e++) acc[i][j][e] = 0.f;

    auto load_tile = [&](int st, int k0) {
        uint32_t base = sm0 + (uint32_t)(st * STAGE_UNITS) * 2;
        #pragma unroll
        for (int j = 0; j < 2; j++) {
            int q = tid + 256 * j;
            int r = q >> 2, c = q & 3;
            cp16(base + (uint32_t)(S_AH + r * ALD2 + c * 8) * 2,
                 Ah + (size_t)(m0 + r) * KP2 + k0 + c * 8);
            cp16(base + (uint32_t)(S_AL + r * ALD2 + c * 8) * 2,
                 Al + (size_t)(m0 + r) * KP2 + k0 + c * 8);
        }
        {
            int r = tid >> 2, c = tid & 3;
            cp16(base + (uint32_t)(S_BH + r * BLD2 + c * 8) * 2,
                 Bh + (size_t)(n0 + r) * KP2 + k0 + c * 8);
            cp16(base + (uint32_t)(S_BL + r * BLD2 + c * 8) * 2,
                 Bl + (size_t)(n0 + r) * KP2 + k0 + c * 8);
        }
    };

    load_tile(0, kbase); cp_commit();
    load_tile(1, kbase + BKT); cp_commit();

    for (int it = 0; it < Ktiles; ++it) {
        if (it + 1 < Ktiles) cp_wait<1>(); else cp_wait<0>();
        __syncthreads();
        if (it + 2 < Ktiles) {
            load_tile((it + 2) % STAGES, kbase + (it + 2) * BKT);
            cp_commit();
        }

        uint32_t stb = sm0 + (uint32_t)((it % STAGES) * STAGE_UNITS) * 2;
        uint32_t bah = stb + (uint32_t)(S_AH + aoff) * 2;
        uint32_t bal = stb + (uint32_t)(S_AL + aoff) * 2;
        uint32_t bbh = stb + (uint32_t)(S_BH + boff) * 2;
        uint32_t bbl = stb + (uint32_t)(S_BL + boff) * 2;

        #pragma unroll
        for (int kk = 0; kk < BKT; kk += 16) {
            uint32_t bh[2][2], bl[2][2];
            #pragma unroll
            for (int j = 0; j < 2; j++) {
                ldsm_x2(bh[j], bbh + (uint32_t)(8 * j * BLD2 + kk) * 2);
                ldsm_x2(bl[j], bbl + (uint32_t)(8 * j * BLD2 + kk) * 2);
            }
            #pragma unroll
            for (int i = 0; i < 4; i++) {
                uint32_t ah[4], al[4];
                ldsm_x4(ah, bah + (uint32_t)(16 * i * ALD2 + kk) * 2);
                ldsm_x4(al, bal + (uint32_t)(16 * i * ALD2 + kk) * 2);
                #pragma unroll
                for (int j = 0; j < 2; j++) {
                    mma16(acc[i][j], ah, bh[j]);
                    mma16(acc[i][j], ah, bl[j]);
                    mma16(acc[i][j], al, bh[j]);
                }
            }
        }
        __syncthreads();
    }

    // epilogue: atomicAdd partials into C (pre-zeroed) + fused s/n partial dots
    float asv[2][2], anv[2][2];
    #pragma unroll
    for (int j = 0; j < 2; j++) {
        int c0 = n0 + wn + 8 * j + 2 * lc;
        asv[j][0] = a_self[c0];     asv[j][1] = a_self[c0 + 1];
        anv[j][0] = a_neigh[c0];    anv[j][1] = a_neigh[c0 + 1];
    }
    #pragma unroll
    for (int i = 0; i < 4; i++) {
        int r0 = m0 + wm + 16 * i + lr;
        float ps0 = 0.f, ps1 = 0.f, pn0 = 0.f, pn1 = 0.f;
        #pragma unroll
        for (int j = 0; j < 2; j++) {
            int c0 = n0 + wn + 8 * j + 2 * lc;
            atomicAdd(&C[(size_t)r0 * 256 + c0],           acc[i][j][0]);
            atomicAdd(&C[(size_t)r0 * 256 + c0 + 1],       acc[i][j][1]);
            atomicAdd(&C[(size_t)(r0 + 8) * 256 + c0],     acc[i][j][2]);
            atomicAdd(&C[(size_t)(r0 + 8) * 256 + c0 + 1], acc[i][j][3]);
            ps0 += acc[i][j][0] * asv[j][0] + acc[i][j][1] * asv[j][1];
            pn0 += acc[i][j][0] * anv[j][0] + acc[i][j][1] * anv[j][1];
            ps1 += acc[i][j][2] * asv[j][0] + acc[i][j][3] * asv[j][1];
            pn1 += acc[i][j][2] * anv[j][0] + acc[i][j][3] * anv[j][1];
        }
        #pragma unroll
        for (int o = 1; o < 4; o <<= 1) {
            ps0 += __shfl_xor_sync(0xffffffffu, ps0, o);
            pn0 += __shfl_xor_sync(0xffffffffu, pn0, o);
            ps1 += __shfl_xor_sync(0xffffffffu, ps1, o);
            pn1 += __shfl_xor_sync(0xffffffffu, pn1, o);
        }
        if (lc == 0) {
            atomicAdd(&s[r0], ps0);     atomicAdd(&n[r0], pn0);
            atomicAdd(&s[r0 + 8], ps1); atomicAdd(&n[r0 + 8], pn1);
        }
    }
}

// -------- fused prep: split x & W1^T to bf16 hi/lo, zero s/n/h1 ----------------
__global__ __launch_bounds__(256) void split_prep_kernel(
    const float* __restrict__ x, const float* __restrict__ W1,
    uint16_t* __restrict__ xh, uint16_t* __restrict__ xl,
    uint16_t* __restrict__ wh, uint16_t* __restrict__ wl,
    float* __restrict__ s, float* __restrict__ n, float* __restrict__ h1zero)
{
    int idx = blockIdx.x * 256 + threadIdx.x;
    if (idx < NND) { s[idx] = 0.f; n[idx] = 0.f; }
    if (idx < NND * HIDD) h1zero[idx] = 0.f;
    if (idx < NND * KP2) {
        int r = idx / KP2, c = idx - r * KP2;
        float v = (c < F_IND) ? x[(size_t)r * F_IND + c] : 0.f;
        uint16_t hi, lo;
        bf16_split(v, hi, lo);
        xh[idx] = hi; xl[idx] = lo;
    } else {
        int idx2 = idx - NND * KP2;
        if (idx2 < HIDD * KP2) {
            int nn = idx2 / KP2, k = idx2 - nn * KP2;
            float v = (k < F_IND) ? W1[(size_t)k * HIDD + nn] : 0.f;
            uint16_t hi, lo;
            bf16_split(v, hi, lo);
            wh[idx2] = hi; wl[idx2] = lo;
        }
    }
}

// ---------------- CSR adjacency build -----------------------------------------
__global__ __launch_bounds__(256) void build_csr(
    const float* __restrict__ adj, int* __restrict__ nidx, int* __restrict__ ncnt)
{
    __shared__ int cnt;
    int row = blockIdx.x;
    if (threadIdx.x == 0) cnt = 0;
    __syncthreads();
    const float4* Ar = reinterpret_cast<const float4*>(adj + (size_t)row * NND);
    for (int j4 = threadIdx.x; j4 < NND / 4; j4 += 256) {
        float4 v = Ar[j4];
        if (v.x > 0.f) { int p = atomicAdd(&cnt, 1); if (p < NNZCAP) nidx[(size_t)row * NNZCAP + p] = j4 * 4; }
        if (v.y > 0.f) { int p = atomicAdd(&cnt, 1); if (p < NNZCAP) nidx[(size_t)row * NNZCAP + p] = j4 * 4 + 1; }
        if (v.z > 0.f) { int p = atomicAdd(&cnt, 1); if (p < NNZCAP) nidx[(size_t)row * NNZCAP + p] = j4 * 4 + 2; }
        if (v.w > 0.f) { int p = atomicAdd(&cnt, 1); if (p < NNZCAP) nidx[(size_t)row * NNZCAP + p] = j4 * 4 + 3; }
    }
    __syncthreads();
    if (threadIdx.x == 0) ncnt[row] = min(cnt, NNZCAP);
}

// ---- fused sparse softmax + SpMM, D=256 --------------------------------------
__global__ __launch_bounds__(256) void sparse_att_h256(
    const float* __restrict__ s, const float* __restrict__ n,
    const float* __restrict__ Mm, const float* __restrict__ h,
    const int* __restrict__ nidx, const int* __restrict__ ncnt,
    float* __restrict__ out)
{
    __shared__ int sidx[NNZCAP];       // pre-scaled: j*256
    __shared__ float slog[NNZCAP];
    __shared__ float red[8];
    int row = blockIdx.x, tid = threadIdx.x;
    int cnt = ncnt[row];
    float si = s[row];
    const float* Mr = Mm + (size_t)row * NND;
    const int* Ir = nidx + (size_t)row * NNZCAP;

    float lmax = -INFINITY;
    for (int t = tid; t < cnt; t += 256) {
        int j = Ir[t];
        sidx[t] = j << 8;
        float l = (si + n[j]) * Mr[j];
        l = (l >= 0.f) ? l : 0.2f * l;
        slog[t] = l;
        lmax = fmaxf(lmax, l);
    }
    lmax = warp_red_max(lmax);
    if ((tid & 31) == 0) red[tid >> 5] = lmax;
    __syncthreads();
    if (tid < 32) {
        float v = (tid < 8) ? red[tid] : -INFINITY;
        v = warp_red_max(v);
        if (tid == 0) red[0] = v;
    }
    __syncthreads();
    lmax = red[0];
    __syncthreads();
    float lsum = 0.f;
    for (int t = tid; t < cnt; t += 256) {
        float e = __expf(slog[t] - lmax);
        slog[t] = e;
        lsum += e;
    }
    lsum = warp_red_sum(lsum);
    if ((tid & 31) == 0) red[tid >> 5] = lsum;
    __syncthreads();
    if (tid < 32) {
        float v = (tid < 8) ? red[tid] : 0.f;
        v = warp_red_sum(v);
        if (tid == 0) red[0] = v;
    }
    __syncthreads();
    float inv = 1.f / red[0];

    float a0 = 0.f, a1 = 0.f, a2 = 0.f, a3 = 0.f;
    int t = 0;
    for (; t + 4 <= cnt; t += 4) {
        a0 += slog[t]     * h[sidx[t]     + tid];
        a1 += slog[t + 1] * h[sidx[t + 1] + tid];
        a2 += slog[t + 2] * h[sidx[t + 2] + tid];
        a3 += slog[t + 3] * h[sidx[t + 3] + tid];
    }
    for (; t < cnt; t++) a0 += slog[t] * h[sidx[t] + tid];
    float acc = ((a0 + a1) + (a2 + a3)) * inv;
    out[(size_t)row * 256 + tid] = (acc > 0.f) ? acc : expm1f(acc);
}

// ---- fused sparse softmax + SpMM D=16 + normalize + Student-t q --------------
__global__ __launch_bounds__(128) void sparse_att_fin(
    const float* __restrict__ s, const float* __restrict__ n,
    const float* __restrict__ Mm, const float* __restrict__ h,
    const int* __restrict__ nidx, const int* __restrict__ ncnt,
    const float* __restrict__ clusters,
    float* __restrict__ z, float* __restrict__ q)
{
    __shared__ int sidx[NNZCAP];       // pre-scaled: j*16
    __shared__ float slog[NNZCAP];
    __shared__ float red[4];
    __shared__ float part[8][16];
    __shared__ float zs[16];
    __shared__ float qs[KCD];
    int row = blockIdx.x, tid = threadIdx.x;
    int cnt = ncnt[row];
    float si = s[row];
    const float* Mr = Mm + (size_t)row * NND;
    const int* Ir = nidx + (size_t)row * NNZCAP;

    float lmax = -INFINITY;
    for (int t = tid; t < cnt; t += 128) {
        int j = Ir[t];
        sidx[t] = j << 4;
        float l = (si + n[j]) * Mr[j];
        l = (l >= 0.f) ? l : 0.2f * l;
        slog[t] = l;
        lmax = fmaxf(lmax, l);
    }
    lmax = warp_red_max(lmax);
    if ((tid & 31) == 0) red[tid >> 5] = lmax;
    __syncthreads();
    if (tid < 32) {
        float v = (tid < 4) ? red[tid] : -INFINITY;
        v = warp_red_max(v);
        if (tid == 0) red[0] = v;
    }
    __syncthreads();
    lmax = red[0];
    __syncthreads();
    float lsum = 0.f;
    for (int t = tid; t < cnt; t += 128) {
        float e = __expf(slog[t] - lmax);
        slog[t] = e;
        lsum += e;
    }
    lsum = warp_red_sum(lsum);
    if ((tid & 31) == 0) red[tid >> 5] = lsum;
    __syncthreads();
    if (tid < 32) {
        float v = (tid < 4) ? red[tid] : 0.f;
        v = warp_red_sum(v);
        if (tid == 0) red[0] = v;
    }
    __syncthreads();
    float inv = 1.f / red[0];

    int p = tid >> 4, d = tid & 15;
    float acc = 0.f;
    for (int t = p; t < cnt; t += 8)
        acc += slog[t] * h[sidx[t] + d];
    part[p][d] = acc;
    __syncthreads();

    if (tid < 16) {
        float a = 0.f;
        #pragma unroll
        for (int pp = 0; pp < 8; pp++) a += part[pp][tid];
        a *= inv;
        float v = (a > 0.f) ? a : expm1f(a);     // h2o value for dim tid
        // L2-normalize across the 16 lanes (all in warp 0)
        float ss = v * v;
        #pragma unroll
        for (int o = 8; o; o >>= 1) ss += __shfl_xor_sync(0xFFFFu, ss, o);
        float zv = v / fmaxf(sqrtf(ss), 1e-12f);
        z[(size_t)row * 16 + tid] = zv;
        zs[tid] = zv;
    }
    __syncwarp(0xFFFFFFFFu);
    if (tid < KCD) {
        float d2 = 0.f;
        #pragma unroll
        for (int dd = 0; dd < 16; dd++) {
            float df = zs[dd] - clusters[tid * 16 + dd];
            d2 += df * df;
        }
        qs[tid] = 1.f / (1.f + d2);
    }
    __syncwarp(0xFFFFFFFFu);
    if (tid < KCD) {
        float sum = 0.f;
        #pragma unroll
        for (int k = 0; k < KCD; k++) sum += qs[k];
        q[(size_t)row * KCD + tid] = qs[tid] / sum;
    }
}

// ---------------- GEMM N=16 (h1o @ W2) + fused rowvec16 -----------------------
__global__ __launch_bounds__(256) void gemm_n16_rv(
    const float* __restrict__ A, const float* __restrict__ B, float* __restrict__ C,
    const float* __restrict__ a_self, const float* __restrict__ a_neigh,
    float* __restrict__ s, float* __restrict__ n)
{
    __shared__ float Bs[256][16];
    int tid = threadIdx.x;
    int r = tid >> 4;
    int c = tid & 15;
    int row = blockIdx.x * 16 + r;
    const float* Arow = A + (size_t)row * HIDD;
    float acc = 0.f;

    #pragma unroll
    for (int i = tid; i < 256 * 16; i += 256)
        Bs[i >> 4][i & 15] = B[i];
    __syncthreads();
    #pragma unroll 8
    for (int kk = 0; kk < HIDD; kk += 4) {
        float4 a = *reinterpret_cast<const float4*>(Arow + kk);
        acc += a.x * Bs[kk][c] + a.y * Bs[kk + 1][c]
             + a.z * Bs[kk + 2][c] + a.w * Bs[kk + 3][c];
    }
    C[(size_t)row * 16 + c] = acc;
    float ps = acc * a_self[c];
    float pn = acc * a_neigh[c];
    #pragma unroll
    for (int o = 8; o; o >>= 1) {
        ps += __shfl_xor_sync(0xffffffffu, ps, o);
        pn += __shfl_xor_sync(0xffffffffu, pn, o);
    }
    if (c == 0) { s[row] = ps; n[row] = pn; }
}

// ---------------- A_pred = sigmoid(z z^T) -------------------------------------
__global__ __launch_bounds__(256) void a_pred_kernel(
    const float* __restrict__ z, float* __restrict__ out)
{
    __shared__ float zi[64][17];
    __shared__ float zj[64][17];
    int bi = blockIdx.y * 64, bj = blockIdx.x * 64;
    for (int i = threadIdx.x; i < 64 * 16; i += 256) {
        int r = i >> 4, c = i & 15;
        zi[r][c] = z[(size_t)(bi + r) * 16 + c];
        zj[r][c] = z[(size_t)(bj + r) * 16 + c];
    }
    __syncthreads();
    int tr = (threadIdx.x >> 4) << 2;
    int tc = (threadIdx.x & 15) << 2;
    float acc[4][4];
    #pragma unroll
    for (int i = 0; i < 4; i++)
        #pragma unroll
        for (int j = 0; j < 4; j++) acc[i][j] = 0.f;
    #pragma unroll
    for (int k = 0; k < 16; k++) {
        float ri[4], rj[4];
        #pragma unroll
        for (int i = 0; i < 4; i++) ri[i] = zi[tr + i][k];
        #pragma unroll
        for (int j = 0; j < 4; j++) rj[j] = zj[tc + j][k];
        #pragma unroll
        for (int i = 0; i < 4; i++)
            #pragma unroll
            for (int j = 0; j < 4; j++) acc[i][j] += ri[i] * rj[j];
    }
    #pragma unroll
    for (int i = 0; i < 4; i++) {
        float4 v;
        v.x = 1.f / (1.f + __expf(-acc[i][0]));
        v.y = 1.f / (1.f + __expf(-acc[i][1]));
        v.z = 1.f / (1.f + __expf(-acc[i][2]));
        v.w = 1.f / (1.f + __expf(-acc[i][3]));
        *reinterpret_cast<float4*>(&out[(size_t)(bi + tr + i) * NND + bj + tc]) = v;
    }
}

// ---------------- launch ------------------------------------------------------
extern "C" void kernel_launch(void* const* d_in, const int* in_sizes, int n_in,
                              void* d_out, int out_size)
{
    const float* x        = (const float*)d_in[0];
    const float* adj      = (const float*)d_in[1];
    const float* Mm       = (const float*)d_in[2];
    const float* W1       = (const float*)d_in[3];
    const float* a_self1  = (const float*)d_in[4];
    const float* a_neigh1 = (const float*)d_in[5];
    const float* W2       = (const float*)d_in[6];
    const float* a_self2  = (const float*)d_in[7];
    const float* a_neigh2 = (const float*)d_in[8];
    const float* clusters = (const float*)d_in[9];

    float* out    = (float*)d_out;
    float* A_pred = out;
    float* z      = out + (size_t)NND * NND;
    float* q      = z + (size_t)NND * EMBD;

    float *h1, *h1o, *h2, *s, *n;
    uint16_t *xh, *xl, *w1h, *w1l;
    int *nidx, *ncnt;
    cudaGetSymbolAddress((void**)&h1,   g_h1);
    cudaGetSymbolAddress((void**)&h1o,  g_h1o);
    cudaGetSymbolAddress((void**)&h2,   g_h2);
    cudaGetSymbolAddress((void**)&s,    g_s);
    cudaGetSymbolAddress((void**)&n,    g_n);
    cudaGetSymbolAddress((void**)&xh,   g_xh);
    cudaGetSymbolAddress((void**)&xl,   g_xl);
    cudaGetSymbolAddress((void**)&w1h,  g_w1h);
    cudaGetSymbolAddress((void**)&w1l,  g_w1l);
    cudaGetSymbolAddress((void**)&nidx, g_nidx);
    cudaGetSymbolAddress((void**)&ncnt, g_ncnt);

    static cudaStream_t s1 = nullptr;
    static cudaEvent_t evF = nullptr, evC = nullptr;
    static bool cfgd = false;
    if (!cfgd) {
        cudaStreamCreateWithFlags(&s1, cudaStreamNonBlocking);
        cudaEventCreateWithFlags(&evF, cudaEventDisableTiming);
        cudaEventCreateWithFlags(&evC, cudaEventDisableTiming);
        cudaFuncSetAttribute(mma_gemm_bf3,
            cudaFuncAttributeMaxDynamicSharedMemorySize, GEMM_SMEM_BYTES);
        cfgd = true;
    }

    // fork: build_csr on side stream
    cudaEventRecord(evF, 0);
    cudaStreamWaitEvent(s1, evF, 0);
    build_csr<<<NND, 256, 0, s1>>>(adj, nidx, ncnt);
    cudaEventRecord(evC, s1);

    // prep (split x, W1; zero s/n/h1) then split-K GEMM
    int prep_elems = NND * KP2 + HIDD * KP2;
    split_prep_kernel<<<(prep_elems + 255) / 256, 256>>>(
        x, W1, xh, xl, w1h, w1l, s, n, h1);
    mma_gemm_bf3<<<dim3(4, 32, 2), 256, GEMM_SMEM_BYTES>>>(
        xh, xl, w1h, w1l, a_self1, a_neigh1, h1, s, n);

    // join
    cudaStreamWaitEvent(0, evC, 0);
    sparse_att_h256<<<NND, 256>>>(s, n, Mm, h1, nidx, ncnt, h1o);

    // Layer 2
    gemm_n16_rv<<<NND / 16, 256>>>(h1o, W2, h2, a_self2, a_neigh2, s, n);
    sparse_att_fin<<<NND, 128>>>(s, n, Mm, h2, nidx, ncnt, clusters, z, q);

    // Outputs
    a_pred_kernel<<<dim3(64, 64), 256>>>(z, A_pred);
}